// round 7
// baseline (speedup 1.0000x reference)
#include <cuda_runtime.h>
#include <math.h>
#include <stddef.h>
#include <stdint.h>

// ---------------- problem constants ----------------
#define TOKS   8192
#define CDIM   768
#define HID    384
#define NHEAD  12
#define HDIM   64
#define SEQ    1024
#define QKVC   2304
#define NBH    96

// ---------------- scratch ---------------------------
__device__ float g_h[(size_t)TOKS * CDIM];
__device__ float g_qkv[(size_t)TOKS * QKVC];
__device__ float g_att[(size_t)TOKS * CDIM];
__device__ float g_x1[(size_t)TOKS * CDIM];
__device__ float g_fc1[(size_t)TOKS * HID];
__device__ float g_wqkv_t[(size_t)QKVC * CDIM];
__device__ float g_wproj_t[(size_t)CDIM * CDIM];
__device__ float g_wfc1_t[(size_t)HID * CDIM];
__device__ float g_wfc2_t[(size_t)CDIM * HID];

typedef unsigned long long u64;

// ---------------- helpers -----------------------
__device__ __forceinline__ uint32_t smem_u32(const void* p) {
    uint32_t a;
    asm("{ .reg .u64 t; cvta.to.shared.u64 t, %1; cvt.u32.u64 %0, t; }" : "=r"(a) : "l"(p));
    return a;
}
__device__ __forceinline__ void cp_async16(uint32_t dst, const void* src) {
    asm volatile("cp.async.cg.shared.global [%0], [%1], 16;" :: "r"(dst), "l"(src));
}
#define CP_COMMIT() asm volatile("cp.async.commit_group;" ::: "memory")
#define SWZ(b) ((b) ^ (((b) >> 3) & 0x70))

__device__ __forceinline__ uint32_t lds32(uint32_t a) {
    uint32_t v;
    asm volatile("ld.shared.b32 %0, [%1];" : "=r"(v) : "r"(a));
    return v;
}

__device__ __forceinline__ void mma_tf32(float* d, const uint32_t* a, const uint32_t* b) {
    asm volatile(
        "mma.sync.aligned.m16n8k8.row.col.f32.tf32.tf32.f32 "
        "{%0,%1,%2,%3}, {%4,%5,%6,%7}, {%8,%9}, {%0,%1,%2,%3};"
        : "+f"(d[0]), "+f"(d[1]), "+f"(d[2]), "+f"(d[3])
        : "r"(a[0]), "r"(a[1]), "r"(a[2]), "r"(a[3]), "r"(b[0]), "r"(b[1]));
}

__device__ __forceinline__ void mma_bf16(float* d, const uint32_t* a, const uint32_t* b) {
    asm volatile(
        "mma.sync.aligned.m16n8k16.row.col.f32.bf16.bf16.f32 "
        "{%0,%1,%2,%3}, {%4,%5,%6,%7}, {%8,%9}, {%0,%1,%2,%3};"
        : "+f"(d[0]), "+f"(d[1]), "+f"(d[2]), "+f"(d[3])
        : "r"(a[0]), "r"(a[1]), "r"(a[2]), "r"(a[3]), "r"(b[0]), "r"(b[1]));
}

// pack two floats (elem k in low, k+1 in high) as bf16x2
__device__ __forceinline__ uint32_t pack_bf16x2(float lo_e, float hi_e) {
    uint32_t r;
    asm("cvt.rn.bf16x2.f32 %0, %1, %2;" : "=r"(r) : "f"(hi_e), "f"(lo_e));
    return r;
}
// split a float pair into bf16 hi pair + bf16 lo(residual) pair
__device__ __forceinline__ void split_bf16(float x, float y, uint32_t &hp, uint32_t &lp) {
    hp = pack_bf16x2(x, y);
    float hx = __uint_as_float(hp << 16);
    float hy = __uint_as_float(hp & 0xffff0000u);
    lp = pack_bf16x2(x - hx, y - hy);
}

// ---------------- weight transpose: out[n,k] = in[k,n] -------------------
__global__ void transpose_kernel(const float* __restrict__ in, float* __restrict__ out,
                                 int K, int N) {
    __shared__ float t[32][33];
    int bn = blockIdx.x << 5, bk = blockIdx.y << 5;
    int tx = threadIdx.x, ty = threadIdx.y;   // 32 x 8
#pragma unroll
    for (int i = 0; i < 4; i++)
        t[ty + i * 8][tx] = in[(size_t)(bk + ty + i * 8) * N + bn + tx];
    __syncthreads();
#pragma unroll
    for (int i = 0; i < 4; i++)
        out[(size_t)(bn + ty + i * 8) * K + bk + tx] = t[tx][ty + i * 8];
}

// ---------------- LayerNorm -------------------------------------------
__global__ void ln_kernel(const float* __restrict__ x, const float* __restrict__ w,
                          const float* __restrict__ b, float* __restrict__ out) {
    int row = blockIdx.x;
    const float* xr = x + (size_t)row * CDIM;
    float* orow = out + (size_t)row * CDIM;
    int t = threadIdx.x;
    float v0 = xr[t], v1 = xr[t + 256], v2 = xr[t + 512];
    float s = v0 + v1 + v2;
    float q = v0 * v0 + v1 * v1 + v2 * v2;
#pragma unroll
    for (int o = 16; o; o >>= 1) {
        s += __shfl_xor_sync(0xffffffffu, s, o);
        q += __shfl_xor_sync(0xffffffffu, q, o);
    }
    __shared__ float rs[8], rq[8];
    if ((t & 31) == 0) { rs[t >> 5] = s; rq[t >> 5] = q; }
    __syncthreads();
    if (t < 32) {
        float us = (t < 8) ? rs[t] : 0.f;
        float uq = (t < 8) ? rq[t] : 0.f;
#pragma unroll
        for (int o = 4; o; o >>= 1) {
            us += __shfl_xor_sync(0xffffffffu, us, o);
            uq += __shfl_xor_sync(0xffffffffu, uq, o);
        }
        if (t == 0) { rs[0] = us; rq[0] = uq; }
    }
    __syncthreads();
    float mu  = rs[0] * (1.f / CDIM);
    float var = rq[0] * (1.f / CDIM) - mu * mu;
    float inv = rsqrtf(var + 1e-5f);
    orow[t]       = (v0 - mu) * inv * w[t]       + b[t];
    orow[t + 256] = (v1 - mu) * inv * w[t + 256] + b[t + 256];
    orow[t + 512] = (v2 - mu) * inv * w[t + 512] + b[t + 512];
}

// ---------------- tf32 mma.sync GEMM, 3-stage cp.async pipeline ----------
#define STG 32768u
__global__ void __launch_bounds__(256)
gemm_mma(const float* __restrict__ A, const float* __restrict__ Bt,
         float* __restrict__ C, int N, int K,
         const float* __restrict__ bias, const float* __restrict__ resid,
         int gelu_flag) {
    extern __shared__ char smem[];
    const uint32_t sb = smem_u32(smem);
    const int tid = threadIdx.x;
    const int wid = tid >> 5, lane = tid & 31;
    const int warp_m = wid & 1, warp_n = wid >> 1;
    const int cl = lane & 3;
    const int r  = lane >> 2;
    const int bn = blockIdx.x << 7, bm = blockIdx.y << 7;

    const int nBK = K >> 5;

    float d[4][4][4];
#pragma unroll
    for (int i = 0; i < 4; i++)
#pragma unroll
        for (int j = 0; j < 4; j++)
#pragma unroll
            for (int e = 0; e < 4; e++) d[i][j][e] = 0.f;

#define LOADT(k0, stg)                                                          \
    {                                                                           \
        uint32_t base = sb + (uint32_t)(stg) * STG;                             \
        _Pragma("unroll")                                                       \
        for (int i = 0; i < 4; i++) {                                           \
            int id = tid + (i << 8);                                            \
            int row = id >> 3, c4 = id & 7;                                     \
            uint32_t byo = (uint32_t)(row * 128 + (c4 << 4));                   \
            uint32_t dst = base + SWZ(byo);                                     \
            cp_async16(dst, A + (size_t)(bm + row) * K + (k0) + (c4 << 2));     \
            cp_async16(dst + 16384u,                                            \
                       Bt + (size_t)(bn + row) * K + (k0) + (c4 << 2));         \
        }                                                                       \
        CP_COMMIT();                                                            \
    }

    LOADT(0, 0);
    LOADT(32, 1);

    const uint32_t swz16 = (uint32_t)r << 4;
    const uint32_t rowa = (uint32_t)(warp_m * 64 + r) * 128u;
    const uint32_t rowb = (uint32_t)(warp_n * 32 + r) * 128u;

    int stage = 0;
    for (int c = 0; c < nBK; c++) {
        if (c == nBK - 1) asm volatile("cp.async.wait_group 0;" ::: "memory");
        else              asm volatile("cp.async.wait_group 1;" ::: "memory");
        __syncthreads();

        if (c + 2 < nBK) {
            int ns = stage + 2; if (ns >= 3) ns -= 3;
            LOADT((c + 2) << 5, ns);
        }

        const uint32_t Ab = sb + (uint32_t)stage * STG + rowa;
        const uint32_t Bb = sb + (uint32_t)stage * STG + 16384u + rowb;

#pragma unroll
        for (int ks = 0; ks < 4; ks++) {
            uint32_t k0x = (uint32_t)((ks * 8 + cl) << 2) ^ swz16;
            uint32_t k1x = (uint32_t)((ks * 8 + cl + 4) << 2) ^ swz16;
            uint32_t av[4][4], bv[4][2];
#pragma unroll
            for (int i = 0; i < 4; i++) {
                uint32_t r0 = Ab + (uint32_t)(i * 16 * 128);
                av[i][0] = lds32(r0 + k0x);
                av[i][1] = lds32(r0 + 8 * 128 + k0x);
                av[i][2] = lds32(r0 + k1x);
                av[i][3] = lds32(r0 + 8 * 128 + k1x);
            }
#pragma unroll
            for (int j = 0; j < 4; j++) {
                uint32_t rb = Bb + (uint32_t)(j * 8 * 128);
                bv[j][0] = lds32(rb + k0x);
                bv[j][1] = lds32(rb + k1x);
            }
#pragma unroll
            for (int i = 0; i < 4; i++)
#pragma unroll
                for (int j = 0; j < 4; j++) mma_tf32(d[i][j], av[i], bv[j]);
        }
        stage++; if (stage == 3) stage = 0;
    }

    const int m0w = bm + warp_m * 64 + r;
    const int n0w = bn + warp_n * 32 + cl * 2;
#pragma unroll
    for (int i = 0; i < 4; i++) {
#pragma unroll
        for (int h = 0; h < 2; h++) {
            int row = m0w + i * 16 + h * 8;
            float* Crow = C + (size_t)row * N;
            const float* Rrow = resid ? resid + (size_t)row * N : (const float*)0;
#pragma unroll
            for (int j = 0; j < 4; j++) {
                int col = n0w + j * 8;
                float v0 = d[i][j][h * 2 + 0];
                float v1 = d[i][j][h * 2 + 1];
                if (bias) { v0 += bias[col]; v1 += bias[col + 1]; }
                if (gelu_flag) {
                    v0 = 0.5f * v0 * (1.f + erff(v0 * 0.70710678118654752f));
                    v1 = 0.5f * v1 * (1.f + erff(v1 * 0.70710678118654752f));
                }
                if (Rrow) { v0 += Rrow[col]; v1 += Rrow[col + 1]; }
                *(float2*)&Crow[col] = make_float2(v0, v1);
            }
        }
    }
#undef LOADT
}
#define GEMM_SMEM (3 * 32768)

// ---------------- flash attention: bf16x3 QK + tf32 PV --------------------
// CTA: 128 q-rows of one (b,h); kv tiles of 64; 8 warps x 16 q-rows.
// Q/K split into bf16 hi+lo pairs (stride 36 u32: conflict-free fragments).
// K/V for tile t+1 prefetched into registers during tile t compute.
#define QS 36   // u32 stride for bf16-pair rows
#define FD 68   // float stride for fp32 tiles

__global__ void __launch_bounds__(256, 1)
flash_mma(const float* __restrict__ qkv, float* __restrict__ att) {
    extern __shared__ char smc[];
    uint32_t* Qhi = (uint32_t*)smc;            // [128][QS]
    uint32_t* Qlo = Qhi + 128 * QS;            // [128][QS]
    uint32_t* Khi = Qlo + 128 * QS;            // [64][QS]
    uint32_t* Klo = Khi + 64 * QS;             // [64][QS]
    float* Vt = (float*)(Klo + 64 * QS);       // [64][FD] (Vt[d][kv])
    float* Ps = Vt + 64 * FD;                  // [128][FD]

    const int tid = threadIdx.x;
    const int wid = tid >> 5, lane = tid & 31;
    const int g = lane >> 2, cl = lane & 3;
    const int qb = blockIdx.x << 7;
    const int bh = blockIdx.y;
    const int b = bh / NHEAD, h = bh % NHEAD;
    const float* qptr = qkv + (size_t)b * SEQ * QKVC + h * HDIM;
    const float* kptr = qptr + CDIM;
    const float* vptr = qptr + 2 * CDIM;

    // ---- load Q (x8 scale), split bf16 hi/lo ----
    {
        int row = tid >> 1;
        const float* src = qptr + (size_t)(qb + row) * QKVC;
#pragma unroll
        for (int e = 0; e < 8; e++) {
            int c4 = ((tid & 1) << 3) + e;
            float4 v = *(const float4*)(src + (c4 << 2));
            v.x *= 8.f; v.y *= 8.f; v.z *= 8.f; v.w *= 8.f;
            uint32_t h0, l0, h1, l1;
            split_bf16(v.x, v.y, h0, l0);
            split_bf16(v.z, v.w, h1, l1);
            Qhi[row * QS + 2 * c4]     = h0;
            Qhi[row * QS + 2 * c4 + 1] = h1;
            Qlo[row * QS + 2 * c4]     = l0;
            Qlo[row * QS + 2 * c4 + 1] = l1;
        }
    }

    float mi0 = -3.4e38f, mi1 = -3.4e38f, li0 = 0.f, li1 = 0.f;
    float o[8][4];
#pragma unroll
    for (int j = 0; j < 8; j++)
#pragma unroll
        for (int e = 0; e < 4; e++) o[j][e] = 0.f;

    const int m0 = wid << 4;
    const int lrow = tid >> 2;          // loader row 0..63
    const int cbase = tid & 3;          // loader float4 col base

    // prefetch tile 0 K/V into registers
    float4 kr[4], vr[4];
    {
        const float* ks = kptr + (size_t)lrow * QKVC;
        const float* vs = vptr + (size_t)lrow * QKVC;
#pragma unroll
        for (int e = 0; e < 4; e++) {
            int c4 = cbase + (e << 2);
            kr[e] = *(const float4*)(ks + (c4 << 2));
            vr[e] = *(const float4*)(vs + (c4 << 2));
        }
    }

    for (int t = 0; t < 16; t++) {
        // ---- convert prefetched K/V into smem ----
#pragma unroll
        for (int e = 0; e < 4; e++) {
            int c4 = cbase + (e << 2);
            uint32_t h0, l0, h1, l1;
            split_bf16(kr[e].x, kr[e].y, h0, l0);
            split_bf16(kr[e].z, kr[e].w, h1, l1);
            Khi[lrow * QS + 2 * c4]     = h0;
            Khi[lrow * QS + 2 * c4 + 1] = h1;
            Klo[lrow * QS + 2 * c4]     = l0;
            Klo[lrow * QS + 2 * c4 + 1] = l1;
            int dc = c4 << 2;
            Vt[(dc + 0) * FD + lrow] = vr[e].x;
            Vt[(dc + 1) * FD + lrow] = vr[e].y;
            Vt[(dc + 2) * FD + lrow] = vr[e].z;
            Vt[(dc + 3) * FD + lrow] = vr[e].w;
        }
        __syncthreads();

        // ---- issue LDGs for tile t+1 (consumed next iteration) ----
        if (t + 1 < 16) {
            const float* ks = kptr + (size_t)(((t + 1) << 6) + lrow) * QKVC;
            const float* vs = vptr + (size_t)(((t + 1) << 6) + lrow) * QKVC;
#pragma unroll
            for (int e = 0; e < 4; e++) {
                int c4 = cbase + (e << 2);
                kr[e] = *(const float4*)(ks + (c4 << 2));
                vr[e] = *(const float4*)(vs + (c4 << 2));
            }
        }

        // ---- S = Q K^T (bf16x3): warp covers 16 q-rows x 64 kv ----
        float s[8][4];
#pragma unroll
        for (int j = 0; j < 8; j++)
#pragma unroll
            for (int e = 0; e < 4; e++) s[j][e] = 0.f;

#pragma unroll
        for (int ks = 0; ks < 4; ks++) {
            int qa = (m0 + g) * QS + (ks << 3) + cl;
            uint32_t ah[4], al[4];
            ah[0] = Qhi[qa];          ah[1] = Qhi[qa + 8 * QS];
            ah[2] = Qhi[qa + 4];      ah[3] = Qhi[qa + 8 * QS + 4];
            al[0] = Qlo[qa];          al[1] = Qlo[qa + 8 * QS];
            al[2] = Qlo[qa + 4];      al[3] = Qlo[qa + 8 * QS + 4];
#pragma unroll
            for (int j = 0; j < 8; j++) {
                int ba = ((j << 3) + g) * QS + (ks << 3) + cl;
                uint32_t bh2[2], bl2[2];
                bh2[0] = Khi[ba]; bh2[1] = Khi[ba + 4];
                bl2[0] = Klo[ba]; bl2[1] = Klo[ba + 4];
                mma_bf16(s[j], ah, bh2);
                mma_bf16(s[j], al, bh2);
                mma_bf16(s[j], ah, bl2);
            }
        }

        // ---- online softmax (rows m0+g and m0+g+8) ----
        float mx0 = s[0][0], mx1 = s[0][2];
#pragma unroll
        for (int j = 0; j < 8; j++) {
            mx0 = fmaxf(mx0, fmaxf(s[j][0], s[j][1]));
            mx1 = fmaxf(mx1, fmaxf(s[j][2], s[j][3]));
        }
        mx0 = fmaxf(mx0, __shfl_xor_sync(0xffffffffu, mx0, 1));
        mx0 = fmaxf(mx0, __shfl_xor_sync(0xffffffffu, mx0, 2));
        mx1 = fmaxf(mx1, __shfl_xor_sync(0xffffffffu, mx1, 1));
        mx1 = fmaxf(mx1, __shfl_xor_sync(0xffffffffu, mx1, 2));
        float mn0 = fmaxf(mi0, mx0), mn1 = fmaxf(mi1, mx1);
        float sc0 = __expf(mi0 - mn0), sc1 = __expf(mi1 - mn1);
        mi0 = mn0; mi1 = mn1;
        float sum0 = 0.f, sum1 = 0.f;
#pragma unroll
        for (int j = 0; j < 8; j++) {
            s[j][0] = __expf(s[j][0] - mn0);
            s[j][1] = __expf(s[j][1] - mn0);
            s[j][2] = __expf(s[j][2] - mn1);
            s[j][3] = __expf(s[j][3] - mn1);
            sum0 += s[j][0] + s[j][1];
            sum1 += s[j][2] + s[j][3];
        }
        sum0 += __shfl_xor_sync(0xffffffffu, sum0, 1);
        sum0 += __shfl_xor_sync(0xffffffffu, sum0, 2);
        sum1 += __shfl_xor_sync(0xffffffffu, sum1, 1);
        sum1 += __shfl_xor_sync(0xffffffffu, sum1, 2);
        li0 = li0 * sc0 + sum0;
        li1 = li1 * sc1 + sum1;
#pragma unroll
        for (int j = 0; j < 8; j++) {
            o[j][0] *= sc0; o[j][1] *= sc0;
            o[j][2] *= sc1; o[j][3] *= sc1;
        }

        // ---- store P (per-warp rows), D->A relayout via smem ----
#pragma unroll
        for (int j = 0; j < 8; j++) {
            *(float2*)&Ps[(m0 + g) * FD + (j << 3) + (cl << 1)] =
                make_float2(s[j][0], s[j][1]);
            *(float2*)&Ps[(m0 + g + 8) * FD + (j << 3) + (cl << 1)] =
                make_float2(s[j][2], s[j][3]);
        }
        __syncwarp();

        // ---- O += P @ V (tf32) ----
#pragma unroll
        for (int ks = 0; ks < 8; ks++) {
            int k0 = ks << 3;
            uint32_t a[4];
            a[0] = __float_as_uint(Ps[(m0 + g) * FD + k0 + cl]);
            a[1] = __float_as_uint(Ps[(m0 + g + 8) * FD + k0 + cl]);
            a[2] = __float_as_uint(Ps[(m0 + g) * FD + k0 + cl + 4]);
            a[3] = __float_as_uint(Ps[(m0 + g + 8) * FD + k0 + cl + 4]);
#pragma unroll
            for (int j = 0; j < 8; j++) {
                uint32_t b2[2];
                b2[0] = __float_as_uint(Vt[((j << 3) + g) * FD + k0 + cl]);
                b2[1] = __float_as_uint(Vt[((j << 3) + g) * FD + k0 + cl + 4]);
                mma_tf32(o[j], a, b2);
            }
        }
        __syncthreads();   // all warps done with Khi/Klo/Vt before overwrite
    }

    // ---- epilogue: O / l -> att in [B,N,C] ----
    {
        float inv0 = 1.f / li0, inv1 = 1.f / li1;
        float* o0 = att + ((size_t)(b * SEQ + qb + m0 + g)) * CDIM + h * HDIM;
        float* o1 = o0 + 8 * CDIM;
#pragma unroll
        for (int j = 0; j < 8; j++) {
            int col = (j << 3) + (cl << 1);
            *(float2*)&o0[col] = make_float2(o[j][0] * inv0, o[j][1] * inv0);
            *(float2*)&o1[col] = make_float2(o[j][2] * inv1, o[j][3] * inv1);
        }
    }
}
#define FLASH_SMEM ((128 * QS * 2 + 64 * QS * 2) * 4 + (64 * FD + 128 * FD) * 4)

// ---------------- launch --------------------------------------------------
extern "C" void kernel_launch(void* const* d_in, const int* in_sizes, int n_in,
                              void* d_out, int out_size) {
    const float* x     = (const float*)d_in[0];
    const float* ln1w  = (const float*)d_in[1];
    const float* ln1b  = (const float*)d_in[2];
    const float* ln2w  = (const float*)d_in[3];
    const float* ln2b  = (const float*)d_in[4];
    const float* wqkv  = (const float*)d_in[5];
    const float* wproj = (const float*)d_in[6];
    const float* wfc1  = (const float*)d_in[7];
    const float* bfc1  = (const float*)d_in[8];
    const float* wfc2  = (const float*)d_in[9];
    const float* bfc2  = (const float*)d_in[10];
    float* out = (float*)d_out;

    float *p_h, *p_qkv, *p_att, *p_x1, *p_fc1;
    float *p_wqkv_t, *p_wproj_t, *p_wfc1_t, *p_wfc2_t;
    cudaGetSymbolAddress((void**)&p_h, g_h);
    cudaGetSymbolAddress((void**)&p_qkv, g_qkv);
    cudaGetSymbolAddress((void**)&p_att, g_att);
    cudaGetSymbolAddress((void**)&p_x1, g_x1);
    cudaGetSymbolAddress((void**)&p_fc1, g_fc1);
    cudaGetSymbolAddress((void**)&p_wqkv_t, g_wqkv_t);
    cudaGetSymbolAddress((void**)&p_wproj_t, g_wproj_t);
    cudaGetSymbolAddress((void**)&p_wfc1_t, g_wfc1_t);
    cudaGetSymbolAddress((void**)&p_wfc2_t, g_wfc2_t);

    cudaFuncSetAttribute(flash_mma, cudaFuncAttributeMaxDynamicSharedMemorySize,
                         FLASH_SMEM);
    cudaFuncSetAttribute(gemm_mma, cudaFuncAttributeMaxDynamicSharedMemorySize,
                         GEMM_SMEM);

    dim3 tb(32, 8);
    transpose_kernel<<<dim3(QKVC / 32, CDIM / 32), tb>>>(wqkv, p_wqkv_t, CDIM, QKVC);
    transpose_kernel<<<dim3(CDIM / 32, CDIM / 32), tb>>>(wproj, p_wproj_t, CDIM, CDIM);
    transpose_kernel<<<dim3(HID / 32, CDIM / 32), tb>>>(wfc1, p_wfc1_t, CDIM, HID);
    transpose_kernel<<<dim3(CDIM / 32, HID / 32), tb>>>(wfc2, p_wfc2_t, HID, CDIM);

    // 1) h = LN1(x)
    ln_kernel<<<TOKS, 256>>>(x, ln1w, ln1b, p_h);
    // 2) qkv = h @ w_qkv
    gemm_mma<<<dim3(QKVC / 128, TOKS / 128), 256, GEMM_SMEM>>>(
        p_h, p_wqkv_t, p_qkv, QKVC, CDIM, nullptr, nullptr, 0);
    // 3-5) fused attention
    flash_mma<<<dim3(SEQ / 128, NBH), 256, FLASH_SMEM>>>(p_qkv, p_att);
    // 6) x1 = x + att @ w_proj
    gemm_mma<<<dim3(CDIM / 128, TOKS / 128), 256, GEMM_SMEM>>>(
        p_att, p_wproj_t, p_x1, CDIM, CDIM, nullptr, x, 0);
    // 7) h = LN2(x1)
    ln_kernel<<<TOKS, 256>>>(p_x1, ln2w, ln2b, p_h);
    // 8) fc1 = gelu(h @ w_fc1 + b_fc1)
    gemm_mma<<<dim3(HID / 128, TOKS / 128), 256, GEMM_SMEM>>>(
        p_h, p_wfc1_t, p_fc1, HID, CDIM, bfc1, nullptr, 1);
    // 9) out = x1 + fc1 @ w_fc2 + b_fc2
    gemm_mma<<<dim3(CDIM / 128, TOKS / 128), 256, GEMM_SMEM>>>(
        p_fc1, p_wfc2_t, out, CDIM, HID, bfc2, p_x1, 0);
}

// round 8
// speedup vs baseline: 1.2394x; 1.2394x over previous
#include <cuda_runtime.h>
#include <math.h>
#include <stddef.h>
#include <stdint.h>

// ---------------- problem constants ----------------
#define TOKS   8192
#define CDIM   768
#define HID    384
#define NHEAD  12
#define HDIM   64
#define SEQ    1024
#define QKVC   2304
#define NBH    96

// ---------------- scratch ---------------------------
__device__ float g_h[(size_t)TOKS * CDIM];
__device__ float g_qkv[(size_t)TOKS * QKVC];
__device__ float g_att[(size_t)TOKS * CDIM];
__device__ float g_x1[(size_t)TOKS * CDIM];
__device__ float g_fc1[(size_t)TOKS * HID];
__device__ float g_wqkv_t[(size_t)QKVC * CDIM];
__device__ float g_wproj_t[(size_t)CDIM * CDIM];
__device__ float g_wfc1_t[(size_t)HID * CDIM];
__device__ float g_wfc2_t[(size_t)CDIM * HID];

typedef unsigned long long u64;

// ---------------- helpers -----------------------
__device__ __forceinline__ uint32_t smem_u32(const void* p) {
    uint32_t a;
    asm("{ .reg .u64 t; cvta.to.shared.u64 t, %1; cvt.u32.u64 %0, t; }" : "=r"(a) : "l"(p));
    return a;
}
__device__ __forceinline__ void cp_async16(uint32_t dst, const void* src) {
    asm volatile("cp.async.cg.shared.global [%0], [%1], 16;" :: "r"(dst), "l"(src));
}
#define CP_COMMIT() asm volatile("cp.async.commit_group;" ::: "memory")
#define SWZ(b) ((b) ^ (((b) >> 3) & 0x70))

__device__ __forceinline__ void lds64(uint32_t a, uint32_t &x, uint32_t &y) {
    asm volatile("ld.shared.v2.b32 {%0,%1}, [%2];" : "=r"(x), "=r"(y) : "r"(a));
}

__device__ __forceinline__ void mma_tf32(float* d, const uint32_t* a, const uint32_t* b) {
    asm volatile(
        "mma.sync.aligned.m16n8k8.row.col.f32.tf32.tf32.f32 "
        "{%0,%1,%2,%3}, {%4,%5,%6,%7}, {%8,%9}, {%0,%1,%2,%3};"
        : "+f"(d[0]), "+f"(d[1]), "+f"(d[2]), "+f"(d[3])
        : "r"(a[0]), "r"(a[1]), "r"(a[2]), "r"(a[3]), "r"(b[0]), "r"(b[1]));
}

__device__ __forceinline__ float cvt_tf32(float x) {
    uint32_t u;
    asm("cvt.rna.tf32.f32 %0, %1;" : "=r"(u) : "f"(x));
    return __uint_as_float(u);
}

// ---------------- weight transpose: out[n,k] = in[k,n] -------------------
__global__ void transpose_kernel(const float* __restrict__ in, float* __restrict__ out,
                                 int K, int N) {
    __shared__ float t[32][33];
    int bn = blockIdx.x << 5, bk = blockIdx.y << 5;
    int tx = threadIdx.x, ty = threadIdx.y;   // 32 x 8
#pragma unroll
    for (int i = 0; i < 4; i++)
        t[ty + i * 8][tx] = in[(size_t)(bk + ty + i * 8) * N + bn + tx];
    __syncthreads();
#pragma unroll
    for (int i = 0; i < 4; i++)
        out[(size_t)(bn + ty + i * 8) * K + bk + tx] = t[tx][ty + i * 8];
}

// ---------------- LayerNorm -------------------------------------------
__global__ void ln_kernel(const float* __restrict__ x, const float* __restrict__ w,
                          const float* __restrict__ b, float* __restrict__ out) {
    int row = blockIdx.x;
    const float* xr = x + (size_t)row * CDIM;
    float* orow = out + (size_t)row * CDIM;
    int t = threadIdx.x;
    float v0 = xr[t], v1 = xr[t + 256], v2 = xr[t + 512];
    float s = v0 + v1 + v2;
    float q = v0 * v0 + v1 * v1 + v2 * v2;
#pragma unroll
    for (int o = 16; o; o >>= 1) {
        s += __shfl_xor_sync(0xffffffffu, s, o);
        q += __shfl_xor_sync(0xffffffffu, q, o);
    }
    __shared__ float rs[8], rq[8];
    if ((t & 31) == 0) { rs[t >> 5] = s; rq[t >> 5] = q; }
    __syncthreads();
    if (t < 32) {
        float us = (t < 8) ? rs[t] : 0.f;
        float uq = (t < 8) ? rq[t] : 0.f;
#pragma unroll
        for (int o = 4; o; o >>= 1) {
            us += __shfl_xor_sync(0xffffffffu, us, o);
            uq += __shfl_xor_sync(0xffffffffu, uq, o);
        }
        if (t == 0) { rs[0] = us; rq[0] = uq; }
    }
    __syncthreads();
    float mu  = rs[0] * (1.f / CDIM);
    float var = rq[0] * (1.f / CDIM) - mu * mu;
    float inv = rsqrtf(var + 1e-5f);
    orow[t]       = (v0 - mu) * inv * w[t]       + b[t];
    orow[t + 256] = (v1 - mu) * inv * w[t + 256] + b[t + 256];
    orow[t + 512] = (v2 - mu) * inv * w[t + 512] + b[t + 512];
}

// ---------------- tf32 mma.sync GEMM, 3-stage pipeline, LDS.64 frags -----
// C[M,N] = A[M,K] @ Bt[N,K]^T. Tile 128x128, BK=32, 8 warps of 64x32.
// k-slot relabeling: MMA slot cl <- logical k 2cl, slot cl+4 <- 2cl+1,
// applied identically to A and B fragments (sum over k invariant), so each
// lane's fragment pair is one ld.shared.v2.b32.
#define STG 32768u
__global__ void __launch_bounds__(256, 2)
gemm_mma(const float* __restrict__ A, const float* __restrict__ Bt,
         float* __restrict__ C, int N, int K,
         const float* __restrict__ bias, const float* __restrict__ resid,
         int gelu_flag) {
    extern __shared__ char smem[];
    const uint32_t sb = smem_u32(smem);
    const int tid = threadIdx.x;
    const int wid = tid >> 5, lane = tid & 31;
    const int warp_m = wid & 1, warp_n = wid >> 1;
    const int cl = lane & 3;
    const int g  = lane >> 2;
    const int bn = blockIdx.x << 7, bm = blockIdx.y << 7;

    const int nBK = K >> 5;

    float d[4][4][4];
#pragma unroll
    for (int i = 0; i < 4; i++)
#pragma unroll
        for (int j = 0; j < 4; j++)
#pragma unroll
            for (int e = 0; e < 4; e++) d[i][j][e] = 0.f;

#define LOADT(k0, stg)                                                          \
    {                                                                           \
        uint32_t base = sb + (uint32_t)(stg) * STG;                             \
        _Pragma("unroll")                                                       \
        for (int i = 0; i < 4; i++) {                                           \
            int id = tid + (i << 8);                                            \
            int row = id >> 3, c4 = id & 7;                                     \
            uint32_t byo = (uint32_t)(row * 128 + (c4 << 4));                   \
            uint32_t dst = base + SWZ(byo);                                     \
            cp_async16(dst, A + (size_t)(bm + row) * K + (k0) + (c4 << 2));     \
            cp_async16(dst + 16384u,                                            \
                       Bt + (size_t)(bn + row) * K + (k0) + (c4 << 2));         \
        }                                                                       \
        CP_COMMIT();                                                            \
    }

    LOADT(0, 0);
    LOADT(32, 1);

    // per-lane fragment-pair byte offsets (swizzle XOR is g<<4 for all our
    // rows since (row & 7) == g for every fragment row this lane touches)
    const uint32_t rowa = (uint32_t)(warp_m * 64 + g) * 128u;
    const uint32_t rowb = (uint32_t)(warp_n * 32 + g) * 128u;
    const uint32_t sx = (uint32_t)g << 4;

    int stage = 0;
    for (int c = 0; c < nBK; c++) {
        if (c == nBK - 1) asm volatile("cp.async.wait_group 0;" ::: "memory");
        else              asm volatile("cp.async.wait_group 1;" ::: "memory");
        __syncthreads();

        if (c + 2 < nBK) {
            int ns = stage + 2; if (ns >= 3) ns -= 3;
            LOADT((c + 2) << 5, ns);
        }

        const uint32_t Ab = sb + (uint32_t)stage * STG + rowa;
        const uint32_t Bb = sb + (uint32_t)stage * STG + 16384u + rowb;

#pragma unroll
        for (int ks = 0; ks < 4; ks++) {
            uint32_t kx = ((uint32_t)((ks * 8 + 2 * cl) << 2)) ^ sx;
            uint32_t av[4][4], bv[4][2];
#pragma unroll
            for (int i = 0; i < 4; i++) {
                uint32_t r0 = Ab + (uint32_t)(i * 16 * 128);
                lds64(r0 + kx, av[i][0], av[i][2]);
                lds64(r0 + 8 * 128 + kx, av[i][1], av[i][3]);
            }
#pragma unroll
            for (int j = 0; j < 4; j++)
                lds64(Bb + (uint32_t)(j * 8 * 128) + kx, bv[j][0], bv[j][1]);
#pragma unroll
            for (int i = 0; i < 4; i++)
#pragma unroll
                for (int j = 0; j < 4; j++) mma_tf32(d[i][j], av[i], bv[j]);
        }
        stage++; if (stage == 3) stage = 0;
    }

    const int m0w = bm + warp_m * 64 + g;
    const int n0w = bn + warp_n * 32 + cl * 2;
#pragma unroll
    for (int i = 0; i < 4; i++) {
#pragma unroll
        for (int h = 0; h < 2; h++) {
            int row = m0w + i * 16 + h * 8;
            float* Crow = C + (size_t)row * N;
            const float* Rrow = resid ? resid + (size_t)row * N : (const float*)0;
#pragma unroll
            for (int j = 0; j < 4; j++) {
                int col = n0w + j * 8;
                float v0 = d[i][j][h * 2 + 0];
                float v1 = d[i][j][h * 2 + 1];
                if (bias) { v0 += bias[col]; v1 += bias[col + 1]; }
                if (gelu_flag) {
                    v0 = 0.5f * v0 * (1.f + erff(v0 * 0.70710678118654752f));
                    v1 = 0.5f * v1 * (1.f + erff(v1 * 0.70710678118654752f));
                }
                if (Rrow) { v0 += Rrow[col]; v1 += Rrow[col + 1]; }
                *(float2*)&Crow[col] = make_float2(v0, v1);
            }
        }
    }
#undef LOADT
}
#define GEMM_SMEM (3 * 32768)

// ---------------- flash attention (R5 version, verbatim) ------------------
#define FD 68

__global__ void __launch_bounds__(256, 1)
flash_mma(const float* __restrict__ qkv, float* __restrict__ att) {
    extern __shared__ float sm[];
    float* Qhi = sm;                     // [128][FD]
    float* Qlo = Qhi + 128 * FD;         // [128][FD]
    float* Khi = Qlo + 128 * FD;         // [64][FD]
    float* Klo = Khi + 64 * FD;          // [64][FD]
    float* Vt  = Klo + 64 * FD;          // [64][FD]  (Vt[d][kv])
    float* Ps  = Vt + 64 * FD;           // [128][FD]

    const int tid = threadIdx.x;
    const int wid = tid >> 5, lane = tid & 31;
    const int r = lane >> 2, cl = lane & 3;
    const int qb = blockIdx.x << 7;
    const int bh = blockIdx.y;
    const int b = bh / NHEAD, h = bh % NHEAD;
    const float* qptr = qkv + (size_t)b * SEQ * QKVC + h * HDIM;
    const float* kptr = qptr + CDIM;
    const float* vptr = qptr + 2 * CDIM;

    {
        int row = tid >> 1;
        const float* src = qptr + (size_t)(qb + row) * QKVC;
#pragma unroll
        for (int e = 0; e < 8; e++) {
            int c4 = ((tid & 1) << 3) + e;
            float4 v = *(const float4*)(src + (c4 << 2));
            v.x *= 8.f; v.y *= 8.f; v.z *= 8.f; v.w *= 8.f;
            float4 hi, lo;
            hi.x = cvt_tf32(v.x); lo.x = v.x - hi.x;
            hi.y = cvt_tf32(v.y); lo.y = v.y - hi.y;
            hi.z = cvt_tf32(v.z); lo.z = v.z - hi.z;
            hi.w = cvt_tf32(v.w); lo.w = v.w - hi.w;
            *(float4*)&Qhi[row * FD + (c4 << 2)] = hi;
            *(float4*)&Qlo[row * FD + (c4 << 2)] = lo;
        }
    }

    float mi0 = -3.4e38f, mi1 = -3.4e38f, li0 = 0.f, li1 = 0.f;
    float o[8][4];
#pragma unroll
    for (int j = 0; j < 8; j++)
#pragma unroll
        for (int e = 0; e < 4; e++) o[j][e] = 0.f;

    const int m0 = wid << 4;

    for (int t = 0; t < 16; t++) {
        __syncthreads();
        {
            int row = tid >> 2;
            const float* ksrc = kptr + (size_t)((t << 6) + row) * QKVC;
            const float* vsrc = vptr + (size_t)((t << 6) + row) * QKVC;
#pragma unroll
            for (int e = 0; e < 4; e++) {
                int c4 = (tid & 3) + (e << 2);
                float4 v = *(const float4*)(ksrc + (c4 << 2));
                float4 hi, lo;
                hi.x = cvt_tf32(v.x); lo.x = v.x - hi.x;
                hi.y = cvt_tf32(v.y); lo.y = v.y - hi.y;
                hi.z = cvt_tf32(v.z); lo.z = v.z - hi.z;
                hi.w = cvt_tf32(v.w); lo.w = v.w - hi.w;
                *(float4*)&Khi[row * FD + (c4 << 2)] = hi;
                *(float4*)&Klo[row * FD + (c4 << 2)] = lo;
                float4 vv = *(const float4*)(vsrc + (c4 << 2));
                int dc = c4 << 2;
                Vt[(dc + 0) * FD + row] = vv.x;
                Vt[(dc + 1) * FD + row] = vv.y;
                Vt[(dc + 2) * FD + row] = vv.z;
                Vt[(dc + 3) * FD + row] = vv.w;
            }
        }
        __syncthreads();

        float s[8][4];
#pragma unroll
        for (int j = 0; j < 8; j++)
#pragma unroll
            for (int e = 0; e < 4; e++) s[j][e] = 0.f;

#pragma unroll
        for (int ks = 0; ks < 8; ks++) {
            int k0 = ks << 3;
            uint32_t ah[4], al[4];
            ah[0] = __float_as_uint(Qhi[(m0 + r) * FD + k0 + cl]);
            ah[1] = __float_as_uint(Qhi[(m0 + r + 8) * FD + k0 + cl]);
            ah[2] = __float_as_uint(Qhi[(m0 + r) * FD + k0 + cl + 4]);
            ah[3] = __float_as_uint(Qhi[(m0 + r + 8) * FD + k0 + cl + 4]);
            al[0] = __float_as_uint(Qlo[(m0 + r) * FD + k0 + cl]);
            al[1] = __float_as_uint(Qlo[(m0 + r + 8) * FD + k0 + cl]);
            al[2] = __float_as_uint(Qlo[(m0 + r) * FD + k0 + cl + 4]);
            al[3] = __float_as_uint(Qlo[(m0 + r + 8) * FD + k0 + cl + 4]);
#pragma unroll
            for (int j = 0; j < 8; j++) {
                int nr = (j << 3) + r;
                uint32_t bh2[2], bl2[2];
                bh2[0] = __float_as_uint(Khi[nr * FD + k0 + cl]);
                bh2[1] = __float_as_uint(Khi[nr * FD + k0 + cl + 4]);
                bl2[0] = __float_as_uint(Klo[nr * FD + k0 + cl]);
                bl2[1] = __float_as_uint(Klo[nr * FD + k0 + cl + 4]);
                mma_tf32(s[j], ah, bh2);
                mma_tf32(s[j], al, bh2);
                mma_tf32(s[j], ah, bl2);
            }
        }

        float mx0 = s[0][0], mx1 = s[0][2];
#pragma unroll
        for (int j = 0; j < 8; j++) {
            mx0 = fmaxf(mx0, fmaxf(s[j][0], s[j][1]));
            mx1 = fmaxf(mx1, fmaxf(s[j][2], s[j][3]));
        }
        mx0 = fmaxf(mx0, __shfl_xor_sync(0xffffffffu, mx0, 1));
        mx0 = fmaxf(mx0, __shfl_xor_sync(0xffffffffu, mx0, 2));
        mx1 = fmaxf(mx1, __shfl_xor_sync(0xffffffffu, mx1, 1));
        mx1 = fmaxf(mx1, __shfl_xor_sync(0xffffffffu, mx1, 2));
        float mn0 = fmaxf(mi0, mx0), mn1 = fmaxf(mi1, mx1);
        float sc0 = __expf(mi0 - mn0), sc1 = __expf(mi1 - mn1);
        mi0 = mn0; mi1 = mn1;
        float sum0 = 0.f, sum1 = 0.f;
#pragma unroll
        for (int j = 0; j < 8; j++) {
            s[j][0] = __expf(s[j][0] - mn0);
            s[j][1] = __expf(s[j][1] - mn0);
            s[j][2] = __expf(s[j][2] - mn1);
            s[j][3] = __expf(s[j][3] - mn1);
            sum0 += s[j][0] + s[j][1];
            sum1 += s[j][2] + s[j][3];
        }
        sum0 += __shfl_xor_sync(0xffffffffu, sum0, 1);
        sum0 += __shfl_xor_sync(0xffffffffu, sum0, 2);
        sum1 += __shfl_xor_sync(0xffffffffu, sum1, 1);
        sum1 += __shfl_xor_sync(0xffffffffu, sum1, 2);
        li0 = li0 * sc0 + sum0;
        li1 = li1 * sc1 + sum1;
#pragma unroll
        for (int j = 0; j < 8; j++) {
            o[j][0] *= sc0; o[j][1] *= sc0;
            o[j][2] *= sc1; o[j][3] *= sc1;
        }

#pragma unroll
        for (int j = 0; j < 8; j++) {
            *(float2*)&Ps[(m0 + r) * FD + (j << 3) + (cl << 1)] =
                make_float2(s[j][0], s[j][1]);
            *(float2*)&Ps[(m0 + r + 8) * FD + (j << 3) + (cl << 1)] =
                make_float2(s[j][2], s[j][3]);
        }
        __syncwarp();

#pragma unroll
        for (int ks = 0; ks < 8; ks++) {
            int k0 = ks << 3;
            uint32_t a[4];
            a[0] = __float_as_uint(Ps[(m0 + r) * FD + k0 + cl]);
            a[1] = __float_as_uint(Ps[(m0 + r + 8) * FD + k0 + cl]);
            a[2] = __float_as_uint(Ps[(m0 + r) * FD + k0 + cl + 4]);
            a[3] = __float_as_uint(Ps[(m0 + r + 8) * FD + k0 + cl + 4]);
#pragma unroll
            for (int j = 0; j < 8; j++) {
                uint32_t b2[2];
                b2[0] = __float_as_uint(Vt[((j << 3) + r) * FD + k0 + cl]);
                b2[1] = __float_as_uint(Vt[((j << 3) + r) * FD + k0 + cl + 4]);
                mma_tf32(o[j], a, b2);
            }
        }
    }

    {
        float inv0 = 1.f / li0, inv1 = 1.f / li1;
        float* o0 = att + ((size_t)(b * SEQ + qb + m0 + r)) * CDIM + h * HDIM;
        float* o1 = o0 + 8 * CDIM;
#pragma unroll
        for (int j = 0; j < 8; j++) {
            int col = (j << 3) + (cl << 1);
            *(float2*)&o0[col] = make_float2(o[j][0] * inv0, o[j][1] * inv0);
            *(float2*)&o1[col] = make_float2(o[j][2] * inv1, o[j][3] * inv1);
        }
    }
}
#define FLASH_SMEM ((128 + 128 + 64 + 64 + 64 + 128) * FD * 4)

// ---------------- launch --------------------------------------------------
extern "C" void kernel_launch(void* const* d_in, const int* in_sizes, int n_in,
                              void* d_out, int out_size) {
    const float* x     = (const float*)d_in[0];
    const float* ln1w  = (const float*)d_in[1];
    const float* ln1b  = (const float*)d_in[2];
    const float* ln2w  = (const float*)d_in[3];
    const float* ln2b  = (const float*)d_in[4];
    const float* wqkv  = (const float*)d_in[5];
    const float* wproj = (const float*)d_in[6];
    const float* wfc1  = (const float*)d_in[7];
    const float* bfc1  = (const float*)d_in[8];
    const float* wfc2  = (const float*)d_in[9];
    const float* bfc2  = (const float*)d_in[10];
    float* out = (float*)d_out;

    float *p_h, *p_qkv, *p_att, *p_x1, *p_fc1;
    float *p_wqkv_t, *p_wproj_t, *p_wfc1_t, *p_wfc2_t;
    cudaGetSymbolAddress((void**)&p_h, g_h);
    cudaGetSymbolAddress((void**)&p_qkv, g_qkv);
    cudaGetSymbolAddress((void**)&p_att, g_att);
    cudaGetSymbolAddress((void**)&p_x1, g_x1);
    cudaGetSymbolAddress((void**)&p_fc1, g_fc1);
    cudaGetSymbolAddress((void**)&p_wqkv_t, g_wqkv_t);
    cudaGetSymbolAddress((void**)&p_wproj_t, g_wproj_t);
    cudaGetSymbolAddress((void**)&p_wfc1_t, g_wfc1_t);
    cudaGetSymbolAddress((void**)&p_wfc2_t, g_wfc2_t);

    cudaFuncSetAttribute(flash_mma, cudaFuncAttributeMaxDynamicSharedMemorySize,
                         FLASH_SMEM);
    cudaFuncSetAttribute(gemm_mma, cudaFuncAttributeMaxDynamicSharedMemorySize,
                         GEMM_SMEM);

    dim3 tb(32, 8);
    // 1) h = LN1(x)   (first so the gemm lands on ncu's skip-5 slot)
    ln_kernel<<<TOKS, 256>>>(x, ln1w, ln1b, p_h);
    transpose_kernel<<<dim3(QKVC / 32, CDIM / 32), tb>>>(wqkv, p_wqkv_t, CDIM, QKVC);
    transpose_kernel<<<dim3(CDIM / 32, CDIM / 32), tb>>>(wproj, p_wproj_t, CDIM, CDIM);
    transpose_kernel<<<dim3(HID / 32, CDIM / 32), tb>>>(wfc1, p_wfc1_t, CDIM, HID);
    transpose_kernel<<<dim3(CDIM / 32, HID / 32), tb>>>(wfc2, p_wfc2_t, HID, CDIM);

    // 2) qkv = h @ w_qkv
    gemm_mma<<<dim3(QKVC / 128, TOKS / 128), 256, GEMM_SMEM>>>(
        p_h, p_wqkv_t, p_qkv, QKVC, CDIM, nullptr, nullptr, 0);
    // 3-5) fused attention
    flash_mma<<<dim3(SEQ / 128, NBH), 256, FLASH_SMEM>>>(p_qkv, p_att);
    // 6) x1 = x + att @ w_proj
    gemm_mma<<<dim3(CDIM / 128, TOKS / 128), 256, GEMM_SMEM>>>(
        p_att, p_wproj_t, p_x1, CDIM, CDIM, nullptr, x, 0);
    // 7) h = LN2(x1)
    ln_kernel<<<TOKS, 256>>>(p_x1, ln2w, ln2b, p_h);
    // 8) fc1 = gelu(h @ w_fc1 + b_fc1)
    gemm_mma<<<dim3(HID / 128, TOKS / 128), 256, GEMM_SMEM>>>(
        p_h, p_wfc1_t, p_fc1, HID, CDIM, bfc1, nullptr, 1);
    // 9) out = x1 + fc1 @ w_fc2 + b_fc2
    gemm_mma<<<dim3(CDIM / 128, TOKS / 128), 256, GEMM_SMEM>>>(
        p_fc1, p_wfc2_t, out, CDIM, HID, bfc2, p_x1, 0);
}

// round 9
// speedup vs baseline: 1.6229x; 1.3094x over previous
#include <cuda_runtime.h>
#include <math.h>
#include <stddef.h>
#include <stdint.h>

// ---------------- problem constants ----------------
#define TOKS   8192
#define CDIM   768
#define HID    384
#define NHEAD  12
#define HDIM   64
#define SEQ    1024
#define QKVC   2304
#define NBH    96

// ---------------- scratch ---------------------------
__device__ float g_h[(size_t)TOKS * CDIM];
__device__ float g_qkv[(size_t)TOKS * QKVC];
__device__ float g_att[(size_t)TOKS * CDIM];
__device__ float g_x1[(size_t)TOKS * CDIM];
__device__ float g_fc1[(size_t)TOKS * HID];
__device__ float g_wqkv_t[(size_t)QKVC * CDIM];
__device__ float g_wproj_t[(size_t)CDIM * CDIM];
__device__ float g_wfc1_t[(size_t)HID * CDIM];
__device__ float g_wfc2_t[(size_t)CDIM * HID];

typedef unsigned long long u64;

// ---------------- helpers -----------------------
__device__ __forceinline__ uint32_t smem_u32(const void* p) {
    uint32_t a;
    asm("{ .reg .u64 t; cvta.to.shared.u64 t, %1; cvt.u32.u64 %0, t; }" : "=r"(a) : "l"(p));
    return a;
}
__device__ __forceinline__ void cp_async16(uint32_t dst, const void* src) {
    asm volatile("cp.async.cg.shared.global [%0], [%1], 16;" :: "r"(dst), "l"(src));
}
#define CP_COMMIT() asm volatile("cp.async.commit_group;" ::: "memory")
#define SWZ(b) ((b) ^ (((b) >> 3) & 0x70))

__device__ __forceinline__ uint32_t lds32(uint32_t a) {
    uint32_t v;
    asm volatile("ld.shared.b32 %0, [%1];" : "=r"(v) : "r"(a));
    return v;
}

__device__ __forceinline__ void mma_tf32(float* d, const uint32_t* a, const uint32_t* b) {
    asm volatile(
        "mma.sync.aligned.m16n8k8.row.col.f32.tf32.tf32.f32 "
        "{%0,%1,%2,%3}, {%4,%5,%6,%7}, {%8,%9}, {%0,%1,%2,%3};"
        : "+f"(d[0]), "+f"(d[1]), "+f"(d[2]), "+f"(d[3])
        : "r"(a[0]), "r"(a[1]), "r"(a[2]), "r"(a[3]), "r"(b[0]), "r"(b[1]));
}

__device__ __forceinline__ void mma_bf16(float* d, const uint32_t* a, const uint32_t* b) {
    asm volatile(
        "mma.sync.aligned.m16n8k16.row.col.f32.bf16.bf16.f32 "
        "{%0,%1,%2,%3}, {%4,%5,%6,%7}, {%8,%9}, {%0,%1,%2,%3};"
        : "+f"(d[0]), "+f"(d[1]), "+f"(d[2]), "+f"(d[3])
        : "r"(a[0]), "r"(a[1]), "r"(a[2]), "r"(a[3]), "r"(b[0]), "r"(b[1]));
}

__device__ __forceinline__ float cvt_tf32(float x) {
    uint32_t u;
    asm("cvt.rna.tf32.f32 %0, %1;" : "=r"(u) : "f"(x));
    return __uint_as_float(u);
}

// pack two floats (x = even k -> low half, y = odd k -> high half) as bf16x2
__device__ __forceinline__ uint32_t pack_bf16x2(float lo_e, float hi_e) {
    uint32_t r;
    asm("cvt.rn.bf16x2.f32 %0, %1, %2;" : "=r"(r) : "f"(hi_e), "f"(lo_e));
    return r;
}
// split a float pair into bf16 hi pair + bf16 lo(residual) pair
__device__ __forceinline__ void split_bf16(float x, float y, uint32_t &hp, uint32_t &lp) {
    hp = pack_bf16x2(x, y);
    float hx = __uint_as_float(hp << 16);
    float hy = __uint_as_float(hp & 0xffff0000u);
    lp = pack_bf16x2(x - hx, y - hy);
}

// ---------------- weight transpose: out[n,k] = in[k,n] -------------------
__global__ void transpose_kernel(const float* __restrict__ in, float* __restrict__ out,
                                 int K, int N) {
    __shared__ float t[32][33];
    int bn = blockIdx.x << 5, bk = blockIdx.y << 5;
    int tx = threadIdx.x, ty = threadIdx.y;   // 32 x 8
#pragma unroll
    for (int i = 0; i < 4; i++)
        t[ty + i * 8][tx] = in[(size_t)(bk + ty + i * 8) * N + bn + tx];
    __syncthreads();
#pragma unroll
    for (int i = 0; i < 4; i++)
        out[(size_t)(bn + ty + i * 8) * K + bk + tx] = t[tx][ty + i * 8];
}

// ---------------- LayerNorm -------------------------------------------
__global__ void ln_kernel(const float* __restrict__ x, const float* __restrict__ w,
                          const float* __restrict__ b, float* __restrict__ out) {
    int row = blockIdx.x;
    const float* xr = x + (size_t)row * CDIM;
    float* orow = out + (size_t)row * CDIM;
    int t = threadIdx.x;
    float v0 = xr[t], v1 = xr[t + 256], v2 = xr[t + 512];
    float s = v0 + v1 + v2;
    float q = v0 * v0 + v1 * v1 + v2 * v2;
#pragma unroll
    for (int o = 16; o; o >>= 1) {
        s += __shfl_xor_sync(0xffffffffu, s, o);
        q += __shfl_xor_sync(0xffffffffu, q, o);
    }
    __shared__ float rs[8], rq[8];
    if ((t & 31) == 0) { rs[t >> 5] = s; rq[t >> 5] = q; }
    __syncthreads();
    if (t < 32) {
        float us = (t < 8) ? rs[t] : 0.f;
        float uq = (t < 8) ? rq[t] : 0.f;
#pragma unroll
        for (int o = 4; o; o >>= 1) {
            us += __shfl_xor_sync(0xffffffffu, us, o);
            uq += __shfl_xor_sync(0xffffffffu, uq, o);
        }
        if (t == 0) { rs[0] = us; rq[0] = uq; }
    }
    __syncthreads();
    float mu  = rs[0] * (1.f / CDIM);
    float var = rq[0] * (1.f / CDIM) - mu * mu;
    float inv = rsqrtf(var + 1e-5f);
    orow[t]       = (v0 - mu) * inv * w[t]       + b[t];
    orow[t + 256] = (v1 - mu) * inv * w[t + 256] + b[t + 256];
    orow[t + 512] = (v2 - mu) * inv * w[t + 512] + b[t + 512];
}

// ---------------- tf32 mma.sync GEMM (R5-measured config, verbatim) ------
__global__ void __launch_bounds__(256)
gemm_mma(const float* __restrict__ A, const float* __restrict__ Bt,
         float* __restrict__ C, int N, int K,
         const float* __restrict__ bias, const float* __restrict__ resid,
         int gelu_flag) {
    extern __shared__ char smem[];
    const uint32_t sb = smem_u32(smem);
    const int tid = threadIdx.x;
    const int wid = tid >> 5, lane = tid & 31;
    const int warp_m = wid & 1, warp_n = wid >> 1;
    const int cl = lane & 3;
    const int r  = lane >> 2;
    const int bn = blockIdx.x << 7, bm = blockIdx.y << 7;

    const int nBK = K >> 5;

    float d[4][4][4];
#pragma unroll
    for (int i = 0; i < 4; i++)
#pragma unroll
        for (int j = 0; j < 4; j++)
#pragma unroll
            for (int e = 0; e < 4; e++) d[i][j][e] = 0.f;

#define LOADT(k0, buf)                                                          \
    {                                                                           \
        uint32_t base = sb + ((buf) ? 32768u : 0u);                             \
        _Pragma("unroll")                                                       \
        for (int i = 0; i < 4; i++) {                                           \
            int id = tid + (i << 8);                                            \
            int row = id >> 3, c4 = id & 7;                                     \
            uint32_t byo = (uint32_t)(row * 128 + (c4 << 4));                   \
            uint32_t dst = base + SWZ(byo);                                     \
            cp_async16(dst, A + (size_t)(bm + row) * K + (k0) + (c4 << 2));     \
            cp_async16(dst + 16384u,                                            \
                       Bt + (size_t)(bn + row) * K + (k0) + (c4 << 2));         \
        }                                                                       \
        CP_COMMIT();                                                            \
    }

    LOADT(0, 0);
    if (nBK > 1) LOADT(32, 1);

    const uint32_t swz16 = (uint32_t)r << 4;
    const uint32_t rowa = (uint32_t)(warp_m * 64 + r) * 128u;
    const uint32_t rowb = (uint32_t)(warp_n * 32 + r) * 128u;

    for (int c = 0; c < nBK; c++) {
        int buf = c & 1;
        if (c == nBK - 1) asm volatile("cp.async.wait_group 0;" ::: "memory");
        else              asm volatile("cp.async.wait_group 1;" ::: "memory");
        __syncthreads();

        const uint32_t Ab = sb + (buf ? 32768u : 0u) + rowa;
        const uint32_t Bb = sb + (buf ? 32768u : 0u) + 16384u + rowb;

#pragma unroll
        for (int ks = 0; ks < 4; ks++) {
            uint32_t k0x = (uint32_t)((ks * 8 + cl) << 2) ^ swz16;
            uint32_t k1x = (uint32_t)((ks * 8 + cl + 4) << 2) ^ swz16;
            uint32_t av[4][4], bv[4][2];
#pragma unroll
            for (int i = 0; i < 4; i++) {
                uint32_t r0 = Ab + (uint32_t)(i * 16 * 128);
                av[i][0] = lds32(r0 + k0x);
                av[i][1] = lds32(r0 + 8 * 128 + k0x);
                av[i][2] = lds32(r0 + k1x);
                av[i][3] = lds32(r0 + 8 * 128 + k1x);
            }
#pragma unroll
            for (int j = 0; j < 4; j++) {
                uint32_t rb = Bb + (uint32_t)(j * 8 * 128);
                bv[j][0] = lds32(rb + k0x);
                bv[j][1] = lds32(rb + k1x);
            }
#pragma unroll
            for (int i = 0; i < 4; i++)
#pragma unroll
                for (int j = 0; j < 4; j++) mma_tf32(d[i][j], av[i], bv[j]);
        }
        __syncthreads();
        if (c + 2 < nBK) LOADT((c + 2) << 5, buf);
    }

    const int m0w = bm + warp_m * 64 + r;
    const int n0w = bn + warp_n * 32 + cl * 2;
#pragma unroll
    for (int i = 0; i < 4; i++) {
#pragma unroll
        for (int h = 0; h < 2; h++) {
            int row = m0w + i * 16 + h * 8;
            float* Crow = C + (size_t)row * N;
            const float* Rrow = resid ? resid + (size_t)row * N : (const float*)0;
#pragma unroll
            for (int j = 0; j < 4; j++) {
                int col = n0w + j * 8;
                float v0 = d[i][j][h * 2 + 0];
                float v1 = d[i][j][h * 2 + 1];
                if (bias) { v0 += bias[col]; v1 += bias[col + 1]; }
                if (gelu_flag) {
                    v0 = 0.5f * v0 * (1.f + erff(v0 * 0.70710678118654752f));
                    v1 = 0.5f * v1 * (1.f + erff(v1 * 0.70710678118654752f));
                }
                if (Rrow) { v0 += Rrow[col]; v1 += Rrow[col + 1]; }
                *(float2*)&Crow[col] = make_float2(v0, v1);
            }
        }
    }
#undef LOADT
}
#define GEMM_SMEM 65536

// ---------------- flash attention: R5 skeleton, bf16x3 QK + tf32 PV ------
// CTA: 128 q-rows of one (b,h); kv tiles of 64; 8 warps x 16 q-rows.
// Q/K stored as bf16-pair u32 arrays, row stride 36 (== 4 mod 32 ->
// fragment loads at bank 4r+cl, conflict-free). Syncs identical to R5.
#define QS 36   // u32 stride for bf16-pair rows
#define FD 68   // float stride for fp32 tiles

__global__ void __launch_bounds__(256, 1)
flash_mma(const float* __restrict__ qkv, float* __restrict__ att) {
    extern __shared__ char smc[];
    uint32_t* Qhb = (uint32_t*)smc;            // [128][QS]
    uint32_t* Qlb = Qhb + 128 * QS;            // [128][QS]
    uint32_t* Khb = Qlb + 128 * QS;            // [64][QS]
    uint32_t* Klb = Khb + 64 * QS;             // [64][QS]
    float* Vt = (float*)(Klb + 64 * QS);       // [64][FD] (Vt[d][kv])
    float* Ps = Vt + 64 * FD;                  // [128][FD]

    const int tid = threadIdx.x;
    const int wid = tid >> 5, lane = tid & 31;
    const int r = lane >> 2, cl = lane & 3;
    const int qb = blockIdx.x << 7;
    const int bh = blockIdx.y;
    const int b = bh / NHEAD, h = bh % NHEAD;
    const float* qptr = qkv + (size_t)b * SEQ * QKVC + h * HDIM;
    const float* kptr = qptr + CDIM;
    const float* vptr = qptr + 2 * CDIM;

    // ---- load Q (x8 scale folded), split bf16 hi/lo pairs ----
    {
        int row = tid >> 1;
        const float* src = qptr + (size_t)(qb + row) * QKVC;
#pragma unroll
        for (int e = 0; e < 8; e++) {
            int c4 = ((tid & 1) << 3) + e;
            float4 v = *(const float4*)(src + (c4 << 2));
            v.x *= 8.f; v.y *= 8.f; v.z *= 8.f; v.w *= 8.f;
            uint32_t h0, l0, h1, l1;
            split_bf16(v.x, v.y, h0, l0);
            split_bf16(v.z, v.w, h1, l1);
            Qhb[row * QS + 2 * c4]     = h0;
            Qhb[row * QS + 2 * c4 + 1] = h1;
            Qlb[row * QS + 2 * c4]     = l0;
            Qlb[row * QS + 2 * c4 + 1] = l1;
        }
    }

    float mi0 = -3.4e38f, mi1 = -3.4e38f, li0 = 0.f, li1 = 0.f;
    float o[8][4];
#pragma unroll
    for (int j = 0; j < 8; j++)
#pragma unroll
        for (int e = 0; e < 4; e++) o[j][e] = 0.f;

    const int m0 = wid << 4;

    for (int t = 0; t < 16; t++) {
        __syncthreads();   // prior PV done before overwriting K/V
        // ---- load K (split bf16 hi/lo) and V (fp32, transposed) ----
        {
            int row = tid >> 2;
            const float* ksrc = kptr + (size_t)((t << 6) + row) * QKVC;
            const float* vsrc = vptr + (size_t)((t << 6) + row) * QKVC;
#pragma unroll
            for (int e = 0; e < 4; e++) {
                int c4 = (tid & 3) + (e << 2);
                float4 v = *(const float4*)(ksrc + (c4 << 2));
                uint32_t h0, l0, h1, l1;
                split_bf16(v.x, v.y, h0, l0);
                split_bf16(v.z, v.w, h1, l1);
                Khb[row * QS + 2 * c4]     = h0;
                Khb[row * QS + 2 * c4 + 1] = h1;
                Klb[row * QS + 2 * c4]     = l0;
                Klb[row * QS + 2 * c4 + 1] = l1;
                float4 vv = *(const float4*)(vsrc + (c4 << 2));
                int dc = c4 << 2;
                Vt[(dc + 0) * FD + row] = vv.x;
                Vt[(dc + 1) * FD + row] = vv.y;
                Vt[(dc + 2) * FD + row] = vv.z;
                Vt[(dc + 3) * FD + row] = vv.w;
            }
        }
        __syncthreads();

        // ---- S = Q K^T (bf16x3, m16n8k16): 4 K-chunks of 16 ----
        float s[8][4];
#pragma unroll
        for (int j = 0; j < 8; j++)
#pragma unroll
            for (int e = 0; e < 4; e++) s[j][e] = 0.f;

#pragma unroll
        for (int ks = 0; ks < 4; ks++) {
            int qa = (m0 + r) * QS + (ks << 3) + cl;
            uint32_t ah[4], al[4];
            ah[0] = Qhb[qa];              ah[1] = Qhb[qa + 8 * QS];
            ah[2] = Qhb[qa + 4];          ah[3] = Qhb[qa + 8 * QS + 4];
            al[0] = Qlb[qa];              al[1] = Qlb[qa + 8 * QS];
            al[2] = Qlb[qa + 4];          al[3] = Qlb[qa + 8 * QS + 4];
#pragma unroll
            for (int j = 0; j < 8; j++) {
                int ba = ((j << 3) + r) * QS + (ks << 3) + cl;
                uint32_t bh2[2], bl2[2];
                bh2[0] = Khb[ba]; bh2[1] = Khb[ba + 4];
                bl2[0] = Klb[ba]; bl2[1] = Klb[ba + 4];
                mma_bf16(s[j], ah, bh2);
                mma_bf16(s[j], al, bh2);
                mma_bf16(s[j], ah, bl2);
            }
        }

        // ---- online softmax (rows m0+r and m0+r+8) ----
        float mx0 = s[0][0], mx1 = s[0][2];
#pragma unroll
        for (int j = 0; j < 8; j++) {
            mx0 = fmaxf(mx0, fmaxf(s[j][0], s[j][1]));
            mx1 = fmaxf(mx1, fmaxf(s[j][2], s[j][3]));
        }
        mx0 = fmaxf(mx0, __shfl_xor_sync(0xffffffffu, mx0, 1));
        mx0 = fmaxf(mx0, __shfl_xor_sync(0xffffffffu, mx0, 2));
        mx1 = fmaxf(mx1, __shfl_xor_sync(0xffffffffu, mx1, 1));
        mx1 = fmaxf(mx1, __shfl_xor_sync(0xffffffffu, mx1, 2));
        float mn0 = fmaxf(mi0, mx0), mn1 = fmaxf(mi1, mx1);
        float sc0 = __expf(mi0 - mn0), sc1 = __expf(mi1 - mn1);
        mi0 = mn0; mi1 = mn1;
        float sum0 = 0.f, sum1 = 0.f;
#pragma unroll
        for (int j = 0; j < 8; j++) {
            s[j][0] = __expf(s[j][0] - mn0);
            s[j][1] = __expf(s[j][1] - mn0);
            s[j][2] = __expf(s[j][2] - mn1);
            s[j][3] = __expf(s[j][3] - mn1);
            sum0 += s[j][0] + s[j][1];
            sum1 += s[j][2] + s[j][3];
        }
        sum0 += __shfl_xor_sync(0xffffffffu, sum0, 1);
        sum0 += __shfl_xor_sync(0xffffffffu, sum0, 2);
        sum1 += __shfl_xor_sync(0xffffffffu, sum1, 1);
        sum1 += __shfl_xor_sync(0xffffffffu, sum1, 2);
        li0 = li0 * sc0 + sum0;
        li1 = li1 * sc1 + sum1;
#pragma unroll
        for (int j = 0; j < 8; j++) {
            o[j][0] *= sc0; o[j][1] *= sc0;
            o[j][2] *= sc1; o[j][3] *= sc1;
        }

        // ---- store P (per-warp rows), D->A relayout via smem ----
#pragma unroll
        for (int j = 0; j < 8; j++) {
            *(float2*)&Ps[(m0 + r) * FD + (j << 3) + (cl << 1)] =
                make_float2(s[j][0], s[j][1]);
            *(float2*)&Ps[(m0 + r + 8) * FD + (j << 3) + (cl << 1)] =
                make_float2(s[j][2], s[j][3]);
        }
        __syncwarp();

        // ---- O += P @ V (tf32 m16n8k8) ----
#pragma unroll
        for (int ks = 0; ks < 8; ks++) {
            int k0 = ks << 3;
            uint32_t a[4];
            a[0] = __float_as_uint(Ps[(m0 + r) * FD + k0 + cl]);
            a[1] = __float_as_uint(Ps[(m0 + r + 8) * FD + k0 + cl]);
            a[2] = __float_as_uint(Ps[(m0 + r) * FD + k0 + cl + 4]);
            a[3] = __float_as_uint(Ps[(m0 + r + 8) * FD + k0 + cl + 4]);
#pragma unroll
            for (int j = 0; j < 8; j++) {
                uint32_t b2[2];
                b2[0] = __float_as_uint(Vt[((j << 3) + r) * FD + k0 + cl]);
                b2[1] = __float_as_uint(Vt[((j << 3) + r) * FD + k0 + cl + 4]);
                mma_tf32(o[j], a, b2);
            }
        }
    }

    // ---- epilogue: O / l -> att in [B,N,C] ----
    {
        float inv0 = 1.f / li0, inv1 = 1.f / li1;
        float* o0 = att + ((size_t)(b * SEQ + qb + m0 + r)) * CDIM + h * HDIM;
        float* o1 = o0 + 8 * CDIM;
#pragma unroll
        for (int j = 0; j < 8; j++) {
            int col = (j << 3) + (cl << 1);
            *(float2*)&o0[col] = make_float2(o[j][0] * inv0, o[j][1] * inv0);
            *(float2*)&o1[col] = make_float2(o[j][2] * inv1, o[j][3] * inv1);
        }
    }
}
#define FLASH_SMEM ((128 * QS * 2 + 64 * QS * 2) * 4 + (64 * FD + 128 * FD) * 4)

// ---------------- launch --------------------------------------------------
extern "C" void kernel_launch(void* const* d_in, const int* in_sizes, int n_in,
                              void* d_out, int out_size) {
    const float* x     = (const float*)d_in[0];
    const float* ln1w  = (const float*)d_in[1];
    const float* ln1b  = (const float*)d_in[2];
    const float* ln2w  = (const float*)d_in[3];
    const float* ln2b  = (const float*)d_in[4];
    const float* wqkv  = (const float*)d_in[5];
    const float* wproj = (const float*)d_in[6];
    const float* wfc1  = (const float*)d_in[7];
    const float* bfc1  = (const float*)d_in[8];
    const float* wfc2  = (const float*)d_in[9];
    const float* bfc2  = (const float*)d_in[10];
    float* out = (float*)d_out;

    float *p_h, *p_qkv, *p_att, *p_x1, *p_fc1;
    float *p_wqkv_t, *p_wproj_t, *p_wfc1_t, *p_wfc2_t;
    cudaGetSymbolAddress((void**)&p_h, g_h);
    cudaGetSymbolAddress((void**)&p_qkv, g_qkv);
    cudaGetSymbolAddress((void**)&p_att, g_att);
    cudaGetSymbolAddress((void**)&p_x1, g_x1);
    cudaGetSymbolAddress((void**)&p_fc1, g_fc1);
    cudaGetSymbolAddress((void**)&p_wqkv_t, g_wqkv_t);
    cudaGetSymbolAddress((void**)&p_wproj_t, g_wproj_t);
    cudaGetSymbolAddress((void**)&p_wfc1_t, g_wfc1_t);
    cudaGetSymbolAddress((void**)&p_wfc2_t, g_wfc2_t);

    cudaFuncSetAttribute(flash_mma, cudaFuncAttributeMaxDynamicSharedMemorySize,
                         FLASH_SMEM);
    cudaFuncSetAttribute(gemm_mma, cudaFuncAttributeMaxDynamicSharedMemorySize,
                         GEMM_SMEM);

    dim3 tb(32, 8);
    transpose_kernel<<<dim3(QKVC / 32, CDIM / 32), tb>>>(wqkv, p_wqkv_t, CDIM, QKVC);
    transpose_kernel<<<dim3(CDIM / 32, CDIM / 32), tb>>>(wproj, p_wproj_t, CDIM, CDIM);
    transpose_kernel<<<dim3(HID / 32, CDIM / 32), tb>>>(wfc1, p_wfc1_t, CDIM, HID);
    transpose_kernel<<<dim3(CDIM / 32, HID / 32), tb>>>(wfc2, p_wfc2_t, HID, CDIM);

    // 1) h = LN1(x)
    ln_kernel<<<TOKS, 256>>>(x, ln1w, ln1b, p_h);
    // 2) qkv = h @ w_qkv
    gemm_mma<<<dim3(QKVC / 128, TOKS / 128), 256, GEMM_SMEM>>>(
        p_h, p_wqkv_t, p_qkv, QKVC, CDIM, nullptr, nullptr, 0);
    // 3-5) fused attention
    flash_mma<<<dim3(SEQ / 128, NBH), 256, FLASH_SMEM>>>(p_qkv, p_att);
    // 6) x1 = x + att @ w_proj
    gemm_mma<<<dim3(CDIM / 128, TOKS / 128), 256, GEMM_SMEM>>>(
        p_att, p_wproj_t, p_x1, CDIM, CDIM, nullptr, x, 0);
    // 7) h = LN2(x1)
    ln_kernel<<<TOKS, 256>>>(p_x1, ln2w, ln2b, p_h);
    // 8) fc1 = gelu(h @ w_fc1 + b_fc1)
    gemm_mma<<<dim3(HID / 128, TOKS / 128), 256, GEMM_SMEM>>>(
        p_h, p_wfc1_t, p_fc1, HID, CDIM, bfc1, nullptr, 1);
    // 9) out = x1 + fc1 @ w_fc2 + b_fc2
    gemm_mma<<<dim3(CDIM / 128, TOKS / 128), 256, GEMM_SMEM>>>(
        p_fc1, p_wfc2_t, out, CDIM, HID, bfc2, p_x1, 0);
}

// round 10
// speedup vs baseline: 1.8793x; 1.1580x over previous
#include <cuda_runtime.h>
#include <cuda_fp16.h>
#include <math.h>
#include <stddef.h>
#include <stdint.h>

// ---------------- problem constants ----------------
#define TOKS   8192
#define CDIM   768
#define HID    384
#define NHEAD  12
#define HDIM   64
#define SEQ    1024
#define QKVC   2304
#define NBH    96

// ---------------- scratch ---------------------------
__device__ __half g_h16[(size_t)TOKS * CDIM];       // LN out (fp16)
__device__ float  g_qkv[(size_t)TOKS * QKVC];       // qkv (fp32, feeds flash)
__device__ __half g_att16[(size_t)TOKS * CDIM];     // attention out (fp16)
__device__ float  g_x1[(size_t)TOKS * CDIM];        // x + proj (fp32)
__device__ __half g_fc1h[(size_t)TOKS * HID];       // gelu(fc1) (fp16)
__device__ __half g_wqkv_h[(size_t)QKVC * CDIM];
__device__ __half g_wproj_h[(size_t)CDIM * CDIM];
__device__ __half g_wfc1_h[(size_t)HID * CDIM];
__device__ __half g_wfc2_h[(size_t)CDIM * HID];

typedef unsigned long long u64;

// ---------------- helpers -----------------------
__device__ __forceinline__ uint32_t smem_u32(const void* p) {
    uint32_t a;
    asm("{ .reg .u64 t; cvta.to.shared.u64 t, %1; cvt.u32.u64 %0, t; }" : "=r"(a) : "l"(p));
    return a;
}
__device__ __forceinline__ void cp_async16(uint32_t dst, const void* src) {
    asm volatile("cp.async.cg.shared.global [%0], [%1], 16;" :: "r"(dst), "l"(src));
}
#define CP_COMMIT() asm volatile("cp.async.commit_group;" ::: "memory")

__device__ __forceinline__ uint32_t lds32(uint32_t a) {
    uint32_t v;
    asm volatile("ld.shared.b32 %0, [%1];" : "=r"(v) : "r"(a));
    return v;
}
__device__ __forceinline__ void sts16(uint32_t a, unsigned short v) {
    asm volatile("st.shared.u16 [%0], %1;" :: "r"(a), "h"(v));
}

__device__ __forceinline__ void mma_fp16(float* d, const uint32_t* a, const uint32_t* b) {
    asm volatile(
        "mma.sync.aligned.m16n8k16.row.col.f32.f16.f16.f32 "
        "{%0,%1,%2,%3}, {%4,%5,%6,%7}, {%8,%9}, {%0,%1,%2,%3};"
        : "+f"(d[0]), "+f"(d[1]), "+f"(d[2]), "+f"(d[3])
        : "r"(a[0]), "r"(a[1]), "r"(a[2]), "r"(a[3]), "r"(b[0]), "r"(b[1]));
}
__device__ __forceinline__ void mma_bf16(float* d, const uint32_t* a, const uint32_t* b) {
    asm volatile(
        "mma.sync.aligned.m16n8k16.row.col.f32.bf16.bf16.f32 "
        "{%0,%1,%2,%3}, {%4,%5,%6,%7}, {%8,%9}, {%0,%1,%2,%3};"
        : "+f"(d[0]), "+f"(d[1]), "+f"(d[2]), "+f"(d[3])
        : "r"(a[0]), "r"(a[1]), "r"(a[2]), "r"(a[3]), "r"(b[0]), "r"(b[1]));
}

// pack: first arg -> low half (even k), second -> high half
__device__ __forceinline__ uint32_t pack_bf16x2(float lo_e, float hi_e) {
    uint32_t r;
    asm("cvt.rn.bf16x2.f32 %0, %1, %2;" : "=r"(r) : "f"(hi_e), "f"(lo_e));
    return r;
}
__device__ __forceinline__ uint32_t pack_half2(float lo_e, float hi_e) {
    uint32_t r;
    asm("cvt.rn.f16x2.f32 %0, %1, %2;" : "=r"(r) : "f"(hi_e), "f"(lo_e));
    return r;
}
__device__ __forceinline__ void split_bf16(float x, float y, uint32_t &hp, uint32_t &lp) {
    hp = pack_bf16x2(x, y);
    float hx = __uint_as_float(hp << 16);
    float hy = __uint_as_float(hp & 0xffff0000u);
    lp = pack_bf16x2(x - hx, y - hy);
}

// ---------------- weight transpose+convert: out[n][k] = fp16(in[k][n]) ----
__global__ void transpose_kernel(const float* __restrict__ in, __half* __restrict__ out,
                                 int K, int N) {
    __shared__ float t[32][33];
    int bn = blockIdx.x << 5, bk = blockIdx.y << 5;
    int tx = threadIdx.x, ty = threadIdx.y;   // 32 x 8
#pragma unroll
    for (int i = 0; i < 4; i++)
        t[ty + i * 8][tx] = in[(size_t)(bk + ty + i * 8) * N + bn + tx];
    __syncthreads();
#pragma unroll
    for (int i = 0; i < 4; i++)
        out[(size_t)(bn + ty + i * 8) * K + bk + tx] = __float2half_rn(t[tx][ty + i * 8]);
}

// ---------------- LayerNorm (fp32 in -> fp16 out) -------------------------
__global__ void ln_kernel(const float* __restrict__ x, const float* __restrict__ w,
                          const float* __restrict__ b, __half* __restrict__ out) {
    int row = blockIdx.x;
    const float* xr = x + (size_t)row * CDIM;
    __half* orow = out + (size_t)row * CDIM;
    int t = threadIdx.x;
    float v0 = xr[t], v1 = xr[t + 256], v2 = xr[t + 512];
    float s = v0 + v1 + v2;
    float q = v0 * v0 + v1 * v1 + v2 * v2;
#pragma unroll
    for (int o = 16; o; o >>= 1) {
        s += __shfl_xor_sync(0xffffffffu, s, o);
        q += __shfl_xor_sync(0xffffffffu, q, o);
    }
    __shared__ float rs[8], rq[8];
    if ((t & 31) == 0) { rs[t >> 5] = s; rq[t >> 5] = q; }
    __syncthreads();
    if (t < 32) {
        float us = (t < 8) ? rs[t] : 0.f;
        float uq = (t < 8) ? rq[t] : 0.f;
#pragma unroll
        for (int o = 4; o; o >>= 1) {
            us += __shfl_xor_sync(0xffffffffu, us, o);
            uq += __shfl_xor_sync(0xffffffffu, uq, o);
        }
        if (t == 0) { rs[0] = us; rq[0] = uq; }
    }
    __syncthreads();
    float mu  = rs[0] * (1.f / CDIM);
    float var = rq[0] * (1.f / CDIM) - mu * mu;
    float inv = rsqrtf(var + 1e-5f);
    orow[t]       = __float2half_rn((v0 - mu) * inv * w[t]       + b[t]);
    orow[t + 256] = __float2half_rn((v1 - mu) * inv * w[t + 256] + b[t + 256]);
    orow[t + 512] = __float2half_rn((v2 - mu) * inv * w[t + 512] + b[t + 512]);
}

// ---------------- fp16 mma.sync GEMM (single pass; == tf32 precision) -----
// C[M,N] = A[M,K] @ Bt[N,K]^T, fp16 operands, f32 accum.
// Tile 128x128, BK=32, 8 warps of 64x32, m16n8k16, 2 ksteps/BK.
// Smem rows: 32 fp16 = 64B data padded to 80B (bank-conflict-free frags).
#define GSTG 20480u
__global__ void __launch_bounds__(256)
gemm_fp16(const __half* __restrict__ A, const __half* __restrict__ Bt,
          float* __restrict__ C, __half* __restrict__ C16, int N, int K,
          const float* __restrict__ bias, const float* __restrict__ resid,
          int gelu_flag) {
    extern __shared__ char smem[];
    const uint32_t sb = smem_u32(smem);
    const int tid = threadIdx.x;
    const int wid = tid >> 5, lane = tid & 31;
    const int warp_m = wid & 1, warp_n = wid >> 1;
    const int cl = lane & 3;
    const int g  = lane >> 2;
    const int bn = blockIdx.x << 7, bm = blockIdx.y << 7;
    const int nBK = K >> 5;

    float d[4][4][4];
#pragma unroll
    for (int i = 0; i < 4; i++)
#pragma unroll
        for (int j = 0; j < 4; j++)
#pragma unroll
            for (int e = 0; e < 4; e++) d[i][j][e] = 0.f;

#define LOADT(k0, buf)                                                          \
    {                                                                           \
        uint32_t base = sb + ((buf) ? GSTG : 0u);                               \
        _Pragma("unroll")                                                       \
        for (int i = 0; i < 2; i++) {                                           \
            int id = tid + (i << 8);                                            \
            int row = id >> 2, ch = id & 3;                                     \
            uint32_t dst = base + (uint32_t)row * 80u + (uint32_t)(ch << 4);    \
            cp_async16(dst, A + (size_t)(bm + row) * K + (k0) + (ch << 3));     \
            cp_async16(dst + 10240u,                                            \
                       Bt + (size_t)(bn + row) * K + (k0) + (ch << 3));         \
        }                                                                       \
        CP_COMMIT();                                                            \
    }

    LOADT(0, 0);
    if (nBK > 1) LOADT(32, 1);

    const uint32_t rowa = (uint32_t)(warp_m * 64 + g) * 80u;
    const uint32_t rowb = 10240u + (uint32_t)(warp_n * 32 + g) * 80u;

    for (int c = 0; c < nBK; c++) {
        int buf = c & 1;
        if (c == nBK - 1) asm volatile("cp.async.wait_group 0;" ::: "memory");
        else              asm volatile("cp.async.wait_group 1;" ::: "memory");
        __syncthreads();

        const uint32_t Ab = sb + (buf ? GSTG : 0u) + rowa;
        const uint32_t Bb = sb + (buf ? GSTG : 0u) + rowb;

#pragma unroll
        for (int ks = 0; ks < 2; ks++) {
            uint32_t kb = (uint32_t)((ks * 8 + cl) << 2);
            uint32_t av[4][4], bv[4][2];
#pragma unroll
            for (int i = 0; i < 4; i++) {
                uint32_t r0 = Ab + (uint32_t)(i * 1280);
                av[i][0] = lds32(r0 + kb);
                av[i][1] = lds32(r0 + 640u + kb);
                av[i][2] = lds32(r0 + kb + 16u);
                av[i][3] = lds32(r0 + 640u + kb + 16u);
            }
#pragma unroll
            for (int j = 0; j < 4; j++) {
                uint32_t rb = Bb + (uint32_t)(j * 640);
                bv[j][0] = lds32(rb + kb);
                bv[j][1] = lds32(rb + kb + 16u);
            }
#pragma unroll
            for (int i = 0; i < 4; i++)
#pragma unroll
                for (int j = 0; j < 4; j++) mma_fp16(d[i][j], av[i], bv[j]);
        }
        __syncthreads();
        if (c + 2 < nBK) LOADT((c + 2) << 5, buf);
    }

    const int m0w = bm + warp_m * 64 + g;
    const int n0w = bn + warp_n * 32 + cl * 2;
#pragma unroll
    for (int i = 0; i < 4; i++) {
#pragma unroll
        for (int h = 0; h < 2; h++) {
            int row = m0w + i * 16 + h * 8;
            const float* Rrow = resid ? resid + (size_t)row * N : (const float*)0;
#pragma unroll
            for (int j = 0; j < 4; j++) {
                int col = n0w + j * 8;
                float v0 = d[i][j][h * 2 + 0];
                float v1 = d[i][j][h * 2 + 1];
                if (bias) { v0 += bias[col]; v1 += bias[col + 1]; }
                if (gelu_flag) {
                    v0 = 0.5f * v0 * (1.f + erff(v0 * 0.70710678118654752f));
                    v1 = 0.5f * v1 * (1.f + erff(v1 * 0.70710678118654752f));
                }
                if (Rrow) { v0 += Rrow[col]; v1 += Rrow[col + 1]; }
                if (C16) {
                    *(uint32_t*)&C16[(size_t)row * N + col] = pack_half2(v0, v1);
                } else {
                    *(float2*)&C[(size_t)row * N + col] = make_float2(v0, v1);
                }
            }
        }
    }
#undef LOADT
}
#define GEMM_SMEM (2 * 20480)

// ---------------- flash attention: bf16x3 QK + fp16 PV --------------------
// CTA: 128 q-rows of one (b,h); kv tiles of 64; 8 warps x 16 q-rows.
// Q/K: bf16 hi/lo pair arrays (stride 36 u32, conflict-free).
// P, V: fp16 pair arrays (stride 36 u32). PV = single fp16 k16
// (same 10-bit mantissa as the tf32 it replaces).
#define QS 36

__global__ void __launch_bounds__(256, 1)
flash_mma(const float* __restrict__ qkv, __half* __restrict__ att16) {
    extern __shared__ char smc[];
    uint32_t* Qhb = (uint32_t*)smc;            // [128][QS]
    uint32_t* Qlb = Qhb + 128 * QS;            // [128][QS]
    uint32_t* Khb = Qlb + 128 * QS;            // [64][QS]
    uint32_t* Klb = Khb + 64 * QS;             // [64][QS]
    uint32_t* Vth = Klb + 64 * QS;             // [64 d][QS] fp16 kv-pairs
    uint32_t* Ph  = Vth + 64 * QS;             // [128 q][QS] fp16 kv-pairs

    const int tid = threadIdx.x;
    const int wid = tid >> 5, lane = tid & 31;
    const int r = lane >> 2, cl = lane & 3;
    const int qb = blockIdx.x << 7;
    const int bh = blockIdx.y;
    const int b = bh / NHEAD, h = bh % NHEAD;
    const float* qptr = qkv + (size_t)b * SEQ * QKVC + h * HDIM;
    const float* kptr = qptr + CDIM;
    const float* vptr = qptr + 2 * CDIM;
    const uint32_t vth_sb = smem_u32(Vth);

    // ---- load Q (x8 scale), split bf16 hi/lo pairs ----
    {
        int row = tid >> 1;
        const float* src = qptr + (size_t)(qb + row) * QKVC;
#pragma unroll
        for (int e = 0; e < 8; e++) {
            int c4 = ((tid & 1) << 3) + e;
            float4 v = *(const float4*)(src + (c4 << 2));
            v.x *= 8.f; v.y *= 8.f; v.z *= 8.f; v.w *= 8.f;
            uint32_t h0, l0, h1, l1;
            split_bf16(v.x, v.y, h0, l0);
            split_bf16(v.z, v.w, h1, l1);
            Qhb[row * QS + 2 * c4]     = h0;
            Qhb[row * QS + 2 * c4 + 1] = h1;
            Qlb[row * QS + 2 * c4]     = l0;
            Qlb[row * QS + 2 * c4 + 1] = l1;
        }
    }

    float mi0 = -3.4e38f, mi1 = -3.4e38f, li0 = 0.f, li1 = 0.f;
    float o[8][4];
#pragma unroll
    for (int j = 0; j < 8; j++)
#pragma unroll
        for (int e = 0; e < 4; e++) o[j][e] = 0.f;

    const int m0 = wid << 4;

    for (int t = 0; t < 16; t++) {
        __syncthreads();   // prior PV done before overwriting K/V
        // ---- load K (bf16 hi/lo) and V (fp16 pairs, transposed) ----
        {
            int row = tid >> 2;
            const float* ksrc = kptr + (size_t)((t << 6) + row) * QKVC;
            const float* vsrc = vptr + (size_t)((t << 6) + row) * QKVC;
            uint32_t vbase = vth_sb + (uint32_t)((row >> 1) << 2) + ((row & 1) << 1);
#pragma unroll
            for (int e = 0; e < 4; e++) {
                int c4 = (tid & 3) + (e << 2);
                float4 v = *(const float4*)(ksrc + (c4 << 2));
                uint32_t h0, l0, h1, l1;
                split_bf16(v.x, v.y, h0, l0);
                split_bf16(v.z, v.w, h1, l1);
                Khb[row * QS + 2 * c4]     = h0;
                Khb[row * QS + 2 * c4 + 1] = h1;
                Klb[row * QS + 2 * c4]     = l0;
                Klb[row * QS + 2 * c4 + 1] = l1;
                float4 vv = *(const float4*)(vsrc + (c4 << 2));
                int dc = c4 << 2;
                sts16(vbase + (uint32_t)((dc + 0) * QS << 2),
                      __half_as_ushort(__float2half_rn(vv.x)));
                sts16(vbase + (uint32_t)((dc + 1) * QS << 2),
                      __half_as_ushort(__float2half_rn(vv.y)));
                sts16(vbase + (uint32_t)((dc + 2) * QS << 2),
                      __half_as_ushort(__float2half_rn(vv.z)));
                sts16(vbase + (uint32_t)((dc + 3) * QS << 2),
                      __half_as_ushort(__float2half_rn(vv.w)));
            }
        }
        __syncthreads();

        // ---- S = Q K^T (bf16x3, m16n8k16) ----
        float s[8][4];
#pragma unroll
        for (int j = 0; j < 8; j++)
#pragma unroll
            for (int e = 0; e < 4; e++) s[j][e] = 0.f;

#pragma unroll
        for (int ks = 0; ks < 4; ks++) {
            int qa = (m0 + r) * QS + (ks << 3) + cl;
            uint32_t ah[4], al[4];
            ah[0] = Qhb[qa];              ah[1] = Qhb[qa + 8 * QS];
            ah[2] = Qhb[qa + 4];          ah[3] = Qhb[qa + 8 * QS + 4];
            al[0] = Qlb[qa];              al[1] = Qlb[qa + 8 * QS];
            al[2] = Qlb[qa + 4];          al[3] = Qlb[qa + 8 * QS + 4];
#pragma unroll
            for (int j = 0; j < 8; j++) {
                int ba = ((j << 3) + r) * QS + (ks << 3) + cl;
                uint32_t bh2[2], bl2[2];
                bh2[0] = Khb[ba]; bh2[1] = Khb[ba + 4];
                bl2[0] = Klb[ba]; bl2[1] = Klb[ba + 4];
                mma_bf16(s[j], ah, bh2);
                mma_bf16(s[j], al, bh2);
                mma_bf16(s[j], ah, bl2);
            }
        }

        // ---- online softmax (rows m0+r and m0+r+8) ----
        float mx0 = s[0][0], mx1 = s[0][2];
#pragma unroll
        for (int j = 0; j < 8; j++) {
            mx0 = fmaxf(mx0, fmaxf(s[j][0], s[j][1]));
            mx1 = fmaxf(mx1, fmaxf(s[j][2], s[j][3]));
        }
        mx0 = fmaxf(mx0, __shfl_xor_sync(0xffffffffu, mx0, 1));
        mx0 = fmaxf(mx0, __shfl_xor_sync(0xffffffffu, mx0, 2));
        mx1 = fmaxf(mx1, __shfl_xor_sync(0xffffffffu, mx1, 1));
        mx1 = fmaxf(mx1, __shfl_xor_sync(0xffffffffu, mx1, 2));
        float mn0 = fmaxf(mi0, mx0), mn1 = fmaxf(mi1, mx1);
        float sc0 = __expf(mi0 - mn0), sc1 = __expf(mi1 - mn1);
        mi0 = mn0; mi1 = mn1;
        float sum0 = 0.f, sum1 = 0.f;
#pragma unroll
        for (int j = 0; j < 8; j++) {
            s[j][0] = __expf(s[j][0] - mn0);
            s[j][1] = __expf(s[j][1] - mn0);
            s[j][2] = __expf(s[j][2] - mn1);
            s[j][3] = __expf(s[j][3] - mn1);
            sum0 += s[j][0] + s[j][1];
            sum1 += s[j][2] + s[j][3];
        }
        sum0 += __shfl_xor_sync(0xffffffffu, sum0, 1);
        sum0 += __shfl_xor_sync(0xffffffffu, sum0, 2);
        sum1 += __shfl_xor_sync(0xffffffffu, sum1, 1);
        sum1 += __shfl_xor_sync(0xffffffffu, sum1, 2);
        li0 = li0 * sc0 + sum0;
        li1 = li1 * sc1 + sum1;
#pragma unroll
        for (int j = 0; j < 8; j++) {
            o[j][0] *= sc0; o[j][1] *= sc0;
            o[j][2] *= sc1; o[j][3] *= sc1;
        }

        // ---- store P as fp16 pairs (pair index = kv/2 = j*4+cl) ----
#pragma unroll
        for (int j = 0; j < 8; j++) {
            Ph[(m0 + r) * QS + (j << 2) + cl]     = pack_half2(s[j][0], s[j][1]);
            Ph[(m0 + r + 8) * QS + (j << 2) + cl] = pack_half2(s[j][2], s[j][3]);
        }
        __syncwarp();

        // ---- O += P @ V (fp16 m16n8k16, 4 k-chunks of 16 kv) ----
#pragma unroll
        for (int ks = 0; ks < 4; ks++) {
            int pa = (m0 + r) * QS + (ks << 3) + cl;
            uint32_t a[4];
            a[0] = Ph[pa];           a[1] = Ph[pa + 8 * QS];
            a[2] = Ph[pa + 4];       a[3] = Ph[pa + 8 * QS + 4];
#pragma unroll
            for (int j = 0; j < 8; j++) {
                int vb = ((j << 3) + r) * QS + (ks << 3) + cl;
                uint32_t b2[2];
                b2[0] = Vth[vb]; b2[1] = Vth[vb + 4];
                mma_fp16(o[j], a, b2);
            }
        }
    }

    // ---- epilogue: O / l -> att16 in [B,N,C] ----
    {
        float inv0 = 1.f / li0, inv1 = 1.f / li1;
        __half* o0 = att16 + ((size_t)(b * SEQ + qb + m0 + r)) * CDIM + h * HDIM;
        __half* o1 = o0 + 8 * CDIM;
#pragma unroll
        for (int j = 0; j < 8; j++) {
            int col = (j << 3) + (cl << 1);
            *(uint32_t*)&o0[col] = pack_half2(o[j][0] * inv0, o[j][1] * inv0);
            *(uint32_t*)&o1[col] = pack_half2(o[j][2] * inv1, o[j][3] * inv1);
        }
    }
}
#define FLASH_SMEM ((128 + 128 + 64 + 64 + 64 + 128) * QS * 4)

// ---------------- launch --------------------------------------------------
extern "C" void kernel_launch(void* const* d_in, const int* in_sizes, int n_in,
                              void* d_out, int out_size) {
    const float* x     = (const float*)d_in[0];
    const float* ln1w  = (const float*)d_in[1];
    const float* ln1b  = (const float*)d_in[2];
    const float* ln2w  = (const float*)d_in[3];
    const float* ln2b  = (const float*)d_in[4];
    const float* wqkv  = (const float*)d_in[5];
    const float* wproj = (const float*)d_in[6];
    const float* wfc1  = (const float*)d_in[7];
    const float* bfc1  = (const float*)d_in[8];
    const float* wfc2  = (const float*)d_in[9];
    const float* bfc2  = (const float*)d_in[10];
    float* out = (float*)d_out;

    __half *p_h16, *p_att16, *p_fc1h, *p_wqkv_h, *p_wproj_h, *p_wfc1_h, *p_wfc2_h;
    float *p_qkv, *p_x1;
    cudaGetSymbolAddress((void**)&p_h16, g_h16);
    cudaGetSymbolAddress((void**)&p_qkv, g_qkv);
    cudaGetSymbolAddress((void**)&p_att16, g_att16);
    cudaGetSymbolAddress((void**)&p_x1, g_x1);
    cudaGetSymbolAddress((void**)&p_fc1h, g_fc1h);
    cudaGetSymbolAddress((void**)&p_wqkv_h, g_wqkv_h);
    cudaGetSymbolAddress((void**)&p_wproj_h, g_wproj_h);
    cudaGetSymbolAddress((void**)&p_wfc1_h, g_wfc1_h);
    cudaGetSymbolAddress((void**)&p_wfc2_h, g_wfc2_h);

    cudaFuncSetAttribute(flash_mma, cudaFuncAttributeMaxDynamicSharedMemorySize,
                         FLASH_SMEM);
    cudaFuncSetAttribute(gemm_fp16, cudaFuncAttributeMaxDynamicSharedMemorySize,
                         GEMM_SMEM);

    dim3 tb(32, 8);
    transpose_kernel<<<dim3(QKVC / 32, CDIM / 32), tb>>>(wqkv, p_wqkv_h, CDIM, QKVC);
    transpose_kernel<<<dim3(CDIM / 32, CDIM / 32), tb>>>(wproj, p_wproj_h, CDIM, CDIM);
    transpose_kernel<<<dim3(HID / 32, CDIM / 32), tb>>>(wfc1, p_wfc1_h, CDIM, HID);
    transpose_kernel<<<dim3(CDIM / 32, HID / 32), tb>>>(wfc2, p_wfc2_h, HID, CDIM);

    // 1) h = LN1(x)  (fp16 out)
    ln_kernel<<<TOKS, 256>>>(x, ln1w, ln1b, p_h16);
    // 2) qkv = h @ w_qkv  (fp32 out, feeds flash)
    gemm_fp16<<<dim3(QKVC / 128, TOKS / 128), 256, GEMM_SMEM>>>(
        p_h16, p_wqkv_h, p_qkv, nullptr, QKVC, CDIM, nullptr, nullptr, 0);
    // 3-5) fused attention (att out fp16)
    flash_mma<<<dim3(SEQ / 128, NBH), 256, FLASH_SMEM>>>(p_qkv, p_att16);
    // 6) x1 = x + att @ w_proj  (fp32 out)
    gemm_fp16<<<dim3(CDIM / 128, TOKS / 128), 256, GEMM_SMEM>>>(
        p_att16, p_wproj_h, p_x1, nullptr, CDIM, CDIM, nullptr, x, 0);
    // 7) h = LN2(x1)  (fp16 out)
    ln_kernel<<<TOKS, 256>>>(p_x1, ln2w, ln2b, p_h16);
    // 8) fc1 = gelu(h @ w_fc1 + b_fc1)  (fp16 out)
    gemm_fp16<<<dim3(HID / 128, TOKS / 128), 256, GEMM_SMEM>>>(
        p_h16, p_wfc1_h, nullptr, p_fc1h, HID, CDIM, bfc1, nullptr, 1);
    // 9) out = x1 + fc1 @ w_fc2 + b_fc2  (fp32 out)
    gemm_fp16<<<dim3(CDIM / 128, TOKS / 128), 256, GEMM_SMEM>>>(
        p_fc1h, p_wfc2_h, out, nullptr, CDIM, HID, bfc2, p_x1, 0);
}

// round 11
// speedup vs baseline: 2.2148x; 1.1785x over previous
#include <cuda_runtime.h>
#include <cuda_fp16.h>
#include <math.h>
#include <stddef.h>
#include <stdint.h>

// ---------------- problem constants ----------------
#define TOKS   8192
#define CDIM   768
#define HID    384
#define NHEAD  12
#define HDIM   64
#define SEQ    1024
#define QKVC   2304
#define NBH    96

// ---------------- scratch ---------------------------
__device__ __half g_h16[(size_t)TOKS * CDIM];
__device__ float  g_qkv[(size_t)TOKS * QKVC];
__device__ __half g_att16[(size_t)TOKS * CDIM];
__device__ float  g_x1[(size_t)TOKS * CDIM];
__device__ __half g_fc1h[(size_t)TOKS * HID];
__device__ __half g_wqkv_h[(size_t)QKVC * CDIM];
__device__ __half g_wproj_h[(size_t)CDIM * CDIM];
__device__ __half g_wfc1_h[(size_t)HID * CDIM];
__device__ __half g_wfc2_h[(size_t)CDIM * HID];

typedef unsigned long long u64;

// ---------------- helpers -----------------------
__device__ __forceinline__ uint32_t smem_u32(const void* p) {
    uint32_t a;
    asm("{ .reg .u64 t; cvta.to.shared.u64 t, %1; cvt.u32.u64 %0, t; }" : "=r"(a) : "l"(p));
    return a;
}
__device__ __forceinline__ void cp_async16(uint32_t dst, const void* src) {
    asm volatile("cp.async.cg.shared.global [%0], [%1], 16;" :: "r"(dst), "l"(src));
}
#define CP_COMMIT() asm volatile("cp.async.commit_group;" ::: "memory")

__device__ __forceinline__ uint32_t lds32(uint32_t a) {
    uint32_t v;
    asm volatile("ld.shared.b32 %0, [%1];" : "=r"(v) : "r"(a));
    return v;
}
__device__ __forceinline__ void sts16(uint32_t a, unsigned short v) {
    asm volatile("st.shared.u16 [%0], %1;" :: "r"(a), "h"(v));
}
__device__ __forceinline__ void ldsm_x4(uint32_t addr, uint32_t &r0, uint32_t &r1,
                                        uint32_t &r2, uint32_t &r3) {
    asm volatile("ldmatrix.sync.aligned.m8n8.x4.shared.b16 {%0,%1,%2,%3}, [%4];"
                 : "=r"(r0), "=r"(r1), "=r"(r2), "=r"(r3) : "r"(addr));
}

__device__ __forceinline__ void mma_fp16(float* d, const uint32_t* a, const uint32_t* b) {
    asm volatile(
        "mma.sync.aligned.m16n8k16.row.col.f32.f16.f16.f32 "
        "{%0,%1,%2,%3}, {%4,%5,%6,%7}, {%8,%9}, {%0,%1,%2,%3};"
        : "+f"(d[0]), "+f"(d[1]), "+f"(d[2]), "+f"(d[3])
        : "r"(a[0]), "r"(a[1]), "r"(a[2]), "r"(a[3]), "r"(b[0]), "r"(b[1]));
}
__device__ __forceinline__ void mma_bf16(float* d, const uint32_t* a, const uint32_t* b) {
    asm volatile(
        "mma.sync.aligned.m16n8k16.row.col.f32.bf16.bf16.f32 "
        "{%0,%1,%2,%3}, {%4,%5,%6,%7}, {%8,%9}, {%0,%1,%2,%3};"
        : "+f"(d[0]), "+f"(d[1]), "+f"(d[2]), "+f"(d[3])
        : "r"(a[0]), "r"(a[1]), "r"(a[2]), "r"(a[3]), "r"(b[0]), "r"(b[1]));
}

__device__ __forceinline__ uint32_t pack_bf16x2(float lo_e, float hi_e) {
    uint32_t r;
    asm("cvt.rn.bf16x2.f32 %0, %1, %2;" : "=r"(r) : "f"(hi_e), "f"(lo_e));
    return r;
}
__device__ __forceinline__ uint32_t pack_half2(float lo_e, float hi_e) {
    uint32_t r;
    asm("cvt.rn.f16x2.f32 %0, %1, %2;" : "=r"(r) : "f"(hi_e), "f"(lo_e));
    return r;
}
__device__ __forceinline__ void split_bf16(float x, float y, uint32_t &hp, uint32_t &lp) {
    hp = pack_bf16x2(x, y);
    float hx = __uint_as_float(hp << 16);
    float hy = __uint_as_float(hp & 0xffff0000u);
    lp = pack_bf16x2(x - hx, y - hy);
}

// ---------------- weight transpose+convert: out[n][k] = fp16(in[k][n]) ----
__global__ void transpose_kernel(const float* __restrict__ in, __half* __restrict__ out,
                                 int K, int N) {
    __shared__ float t[32][33];
    int bn = blockIdx.x << 5, bk = blockIdx.y << 5;
    int tx = threadIdx.x, ty = threadIdx.y;   // 32 x 8
#pragma unroll
    for (int i = 0; i < 4; i++)
        t[ty + i * 8][tx] = in[(size_t)(bk + ty + i * 8) * N + bn + tx];
    __syncthreads();
#pragma unroll
    for (int i = 0; i < 4; i++)
        out[(size_t)(bn + ty + i * 8) * K + bk + tx] = __float2half_rn(t[tx][ty + i * 8]);
}

// ---------------- LayerNorm (fp32 in -> fp16 out) -------------------------
__global__ void ln_kernel(const float* __restrict__ x, const float* __restrict__ w,
                          const float* __restrict__ b, __half* __restrict__ out) {
    int row = blockIdx.x;
    const float* xr = x + (size_t)row * CDIM;
    __half* orow = out + (size_t)row * CDIM;
    int t = threadIdx.x;
    float v0 = xr[t], v1 = xr[t + 256], v2 = xr[t + 512];
    float s = v0 + v1 + v2;
    float q = v0 * v0 + v1 * v1 + v2 * v2;
#pragma unroll
    for (int o = 16; o; o >>= 1) {
        s += __shfl_xor_sync(0xffffffffu, s, o);
        q += __shfl_xor_sync(0xffffffffu, q, o);
    }
    __shared__ float rs[8], rq[8];
    if ((t & 31) == 0) { rs[t >> 5] = s; rq[t >> 5] = q; }
    __syncthreads();
    if (t < 32) {
        float us = (t < 8) ? rs[t] : 0.f;
        float uq = (t < 8) ? rq[t] : 0.f;
#pragma unroll
        for (int o = 4; o; o >>= 1) {
            us += __shfl_xor_sync(0xffffffffu, us, o);
            uq += __shfl_xor_sync(0xffffffffu, uq, o);
        }
        if (t == 0) { rs[0] = us; rq[0] = uq; }
    }
    __syncthreads();
    float mu  = rs[0] * (1.f / CDIM);
    float var = rq[0] * (1.f / CDIM) - mu * mu;
    float inv = rsqrtf(var + 1e-5f);
    orow[t]       = __float2half_rn((v0 - mu) * inv * w[t]       + b[t]);
    orow[t + 256] = __float2half_rn((v1 - mu) * inv * w[t + 256] + b[t + 256]);
    orow[t + 512] = __float2half_rn((v2 - mu) * inv * w[t + 512] + b[t + 512]);
}

// ---------------- fp16 GEMM with ldmatrix fragments -----------------------
// C[M,N] = A[M,K] @ Bt[N,K]^T, fp16 ops, f32 accum, m16n8k16.
// Tile 128x128, BK=32 (= 64B/row), 8 warps of 64x32.
// Smem layout: row*64 + ((kh ^ ((row>>1)&3)) << 4), kh = 16B chunk 0..3.
//  -> cp.async 16B writes and 8-lane ldmatrix phases both conflict-free.
#define GSTG 16384u
__global__ void __launch_bounds__(256)
gemm_fp16(const __half* __restrict__ A, const __half* __restrict__ Bt,
          float* __restrict__ C, __half* __restrict__ C16, int N, int K,
          const float* __restrict__ bias, const float* __restrict__ resid,
          int gelu_flag) {
    extern __shared__ char smem[];
    const uint32_t sb = smem_u32(smem);
    const int tid = threadIdx.x;
    const int wid = tid >> 5, lane = tid & 31;
    const int warp_m = wid & 1, warp_n = wid >> 1;
    const int cl = lane & 3;
    const int g  = lane >> 2;
    const int bn = blockIdx.x << 7, bm = blockIdx.y << 7;
    const int nBK = K >> 5;

    float d[4][4][4];
#pragma unroll
    for (int i = 0; i < 4; i++)
#pragma unroll
        for (int j = 0; j < 4; j++)
#pragma unroll
            for (int e = 0; e < 4; e++) d[i][j][e] = 0.f;

#define LOADT(k0, buf)                                                          \
    {                                                                           \
        uint32_t base = sb + ((buf) ? GSTG : 0u);                               \
        _Pragma("unroll")                                                       \
        for (int i = 0; i < 2; i++) {                                           \
            int id = tid + (i << 8);                                            \
            int row = id >> 2, kh = id & 3;                                     \
            uint32_t dst = base + (uint32_t)(row << 6)                          \
                         + (uint32_t)((kh ^ ((row >> 1) & 3)) << 4);            \
            cp_async16(dst, A + (size_t)(bm + row) * K + (k0) + (kh << 3));     \
            cp_async16(dst + 8192u,                                             \
                       Bt + (size_t)(bn + row) * K + (k0) + (kh << 3));         \
        }                                                                       \
        CP_COMMIT();                                                            \
    }

    LOADT(0, 0);
    if (nBK > 1) LOADT(32, 1);

    // ldmatrix lane geometry: within a 16-row fragment, this lane addresses
    // row ar = (lane&7) + ((lane>>3)&1)*8, k-chunk half khp = lane>>4.
    const int ar  = (lane & 7) + (((lane >> 3) & 1) << 3);
    const int khp = lane >> 4;
    const int rowa = warp_m * 64 + ar;        // A row for mi=0
    const int rowb = warp_n * 32 + ar;        // B row for j2=0
    const uint32_t swa = (uint32_t)((rowa >> 1) & 3);
    const uint32_t swb = (uint32_t)((rowb >> 1) & 3);

    for (int c = 0; c < nBK; c++) {
        int buf = c & 1;
        if (c == nBK - 1) asm volatile("cp.async.wait_group 0;" ::: "memory");
        else              asm volatile("cp.async.wait_group 1;" ::: "memory");
        __syncthreads();

        const uint32_t Sb = sb + (buf ? GSTG : 0u);
        const uint32_t Ab = Sb + (uint32_t)(rowa << 6);
        const uint32_t Bb = Sb + 8192u + (uint32_t)(rowb << 6);

#pragma unroll
        for (int ks = 0; ks < 2; ks++) {
            uint32_t kha = (uint32_t)(((2 * ks + khp) ^ swa) << 4);
            uint32_t khb = (uint32_t)(((2 * ks + khp) ^ swb) << 4);
            uint32_t av[4][4], bv[4][2];
#pragma unroll
            for (int mi = 0; mi < 4; mi++)
                ldsm_x4(Ab + (uint32_t)(mi << 10) + kha,
                        av[mi][0], av[mi][1], av[mi][2], av[mi][3]);
#pragma unroll
            for (int j2 = 0; j2 < 2; j2++)
                ldsm_x4(Bb + (uint32_t)(j2 << 10) + khb,
                        bv[j2 * 2][0], bv[j2 * 2 + 1][0],
                        bv[j2 * 2][1], bv[j2 * 2 + 1][1]);
#pragma unroll
            for (int i = 0; i < 4; i++)
#pragma unroll
                for (int j = 0; j < 4; j++) mma_fp16(d[i][j], av[i], bv[j]);
        }
        __syncthreads();
        if (c + 2 < nBK) LOADT((c + 2) << 5, buf);
    }

    const int m0w = bm + warp_m * 64 + g;
    const int n0w = bn + warp_n * 32 + cl * 2;
#pragma unroll
    for (int i = 0; i < 4; i++) {
#pragma unroll
        for (int h = 0; h < 2; h++) {
            int row = m0w + i * 16 + h * 8;
            const float* Rrow = resid ? resid + (size_t)row * N : (const float*)0;
#pragma unroll
            for (int j = 0; j < 4; j++) {
                int col = n0w + j * 8;
                float v0 = d[i][j][h * 2 + 0];
                float v1 = d[i][j][h * 2 + 1];
                if (bias) { v0 += bias[col]; v1 += bias[col + 1]; }
                if (gelu_flag) {
                    v0 = 0.5f * v0 * (1.f + erff(v0 * 0.70710678118654752f));
                    v1 = 0.5f * v1 * (1.f + erff(v1 * 0.70710678118654752f));
                }
                if (Rrow) { v0 += Rrow[col]; v1 += Rrow[col + 1]; }
                if (C16) {
                    *(uint32_t*)&C16[(size_t)row * N + col] = pack_half2(v0, v1);
                } else {
                    *(float2*)&C[(size_t)row * N + col] = make_float2(v0, v1);
                }
            }
        }
    }
#undef LOADT
}
#define GEMM_SMEM (2 * 16384)

// ---------------- flash attention (R10 version, verbatim) -----------------
#define QS 36

__global__ void __launch_bounds__(256, 1)
flash_mma(const float* __restrict__ qkv, __half* __restrict__ att16) {
    extern __shared__ char smc[];
    uint32_t* Qhb = (uint32_t*)smc;            // [128][QS]
    uint32_t* Qlb = Qhb + 128 * QS;            // [128][QS]
    uint32_t* Khb = Qlb + 128 * QS;            // [64][QS]
    uint32_t* Klb = Khb + 64 * QS;             // [64][QS]
    uint32_t* Vth = Klb + 64 * QS;             // [64 d][QS] fp16 kv-pairs
    uint32_t* Ph  = Vth + 64 * QS;             // [128 q][QS] fp16 kv-pairs

    const int tid = threadIdx.x;
    const int wid = tid >> 5, lane = tid & 31;
    const int r = lane >> 2, cl = lane & 3;
    const int qb = blockIdx.x << 7;
    const int bh = blockIdx.y;
    const int b = bh / NHEAD, h = bh % NHEAD;
    const float* qptr = qkv + (size_t)b * SEQ * QKVC + h * HDIM;
    const float* kptr = qptr + CDIM;
    const float* vptr = qptr + 2 * CDIM;
    const uint32_t vth_sb = smem_u32(Vth);

    {
        int row = tid >> 1;
        const float* src = qptr + (size_t)(qb + row) * QKVC;
#pragma unroll
        for (int e = 0; e < 8; e++) {
            int c4 = ((tid & 1) << 3) + e;
            float4 v = *(const float4*)(src + (c4 << 2));
            v.x *= 8.f; v.y *= 8.f; v.z *= 8.f; v.w *= 8.f;
            uint32_t h0, l0, h1, l1;
            split_bf16(v.x, v.y, h0, l0);
            split_bf16(v.z, v.w, h1, l1);
            Qhb[row * QS + 2 * c4]     = h0;
            Qhb[row * QS + 2 * c4 + 1] = h1;
            Qlb[row * QS + 2 * c4]     = l0;
            Qlb[row * QS + 2 * c4 + 1] = l1;
        }
    }

    float mi0 = -3.4e38f, mi1 = -3.4e38f, li0 = 0.f, li1 = 0.f;
    float o[8][4];
#pragma unroll
    for (int j = 0; j < 8; j++)
#pragma unroll
        for (int e = 0; e < 4; e++) o[j][e] = 0.f;

    const int m0 = wid << 4;

    for (int t = 0; t < 16; t++) {
        __syncthreads();
        {
            int row = tid >> 2;
            const float* ksrc = kptr + (size_t)((t << 6) + row) * QKVC;
            const float* vsrc = vptr + (size_t)((t << 6) + row) * QKVC;
            uint32_t vbase = vth_sb + (uint32_t)((row >> 1) << 2) + ((row & 1) << 1);
#pragma unroll
            for (int e = 0; e < 4; e++) {
                int c4 = (tid & 3) + (e << 2);
                float4 v = *(const float4*)(ksrc + (c4 << 2));
                uint32_t h0, l0, h1, l1;
                split_bf16(v.x, v.y, h0, l0);
                split_bf16(v.z, v.w, h1, l1);
                Khb[row * QS + 2 * c4]     = h0;
                Khb[row * QS + 2 * c4 + 1] = h1;
                Klb[row * QS + 2 * c4]     = l0;
                Klb[row * QS + 2 * c4 + 1] = l1;
                float4 vv = *(const float4*)(vsrc + (c4 << 2));
                int dc = c4 << 2;
                sts16(vbase + (uint32_t)((dc + 0) * QS << 2),
                      __half_as_ushort(__float2half_rn(vv.x)));
                sts16(vbase + (uint32_t)((dc + 1) * QS << 2),
                      __half_as_ushort(__float2half_rn(vv.y)));
                sts16(vbase + (uint32_t)((dc + 2) * QS << 2),
                      __half_as_ushort(__float2half_rn(vv.z)));
                sts16(vbase + (uint32_t)((dc + 3) * QS << 2),
                      __half_as_ushort(__float2half_rn(vv.w)));
            }
        }
        __syncthreads();

        float s[8][4];
#pragma unroll
        for (int j = 0; j < 8; j++)
#pragma unroll
            for (int e = 0; e < 4; e++) s[j][e] = 0.f;

#pragma unroll
        for (int ks = 0; ks < 4; ks++) {
            int qa = (m0 + r) * QS + (ks << 3) + cl;
            uint32_t ah[4], al[4];
            ah[0] = Qhb[qa];              ah[1] = Qhb[qa + 8 * QS];
            ah[2] = Qhb[qa + 4];          ah[3] = Qhb[qa + 8 * QS + 4];
            al[0] = Qlb[qa];              al[1] = Qlb[qa + 8 * QS];
            al[2] = Qlb[qa + 4];          al[3] = Qlb[qa + 8 * QS + 4];
#pragma unroll
            for (int j = 0; j < 8; j++) {
                int ba = ((j << 3) + r) * QS + (ks << 3) + cl;
                uint32_t bh2[2], bl2[2];
                bh2[0] = Khb[ba]; bh2[1] = Khb[ba + 4];
                bl2[0] = Klb[ba]; bl2[1] = Klb[ba + 4];
                mma_bf16(s[j], ah, bh2);
                mma_bf16(s[j], al, bh2);
                mma_bf16(s[j], ah, bl2);
            }
        }

        float mx0 = s[0][0], mx1 = s[0][2];
#pragma unroll
        for (int j = 0; j < 8; j++) {
            mx0 = fmaxf(mx0, fmaxf(s[j][0], s[j][1]));
            mx1 = fmaxf(mx1, fmaxf(s[j][2], s[j][3]));
        }
        mx0 = fmaxf(mx0, __shfl_xor_sync(0xffffffffu, mx0, 1));
        mx0 = fmaxf(mx0, __shfl_xor_sync(0xffffffffu, mx0, 2));
        mx1 = fmaxf(mx1, __shfl_xor_sync(0xffffffffu, mx1, 1));
        mx1 = fmaxf(mx1, __shfl_xor_sync(0xffffffffu, mx1, 2));
        float mn0 = fmaxf(mi0, mx0), mn1 = fmaxf(mi1, mx1);
        float sc0 = __expf(mi0 - mn0), sc1 = __expf(mi1 - mn1);
        mi0 = mn0; mi1 = mn1;
        float sum0 = 0.f, sum1 = 0.f;
#pragma unroll
        for (int j = 0; j < 8; j++) {
            s[j][0] = __expf(s[j][0] - mn0);
            s[j][1] = __expf(s[j][1] - mn0);
            s[j][2] = __expf(s[j][2] - mn1);
            s[j][3] = __expf(s[j][3] - mn1);
            sum0 += s[j][0] + s[j][1];
            sum1 += s[j][2] + s[j][3];
        }
        sum0 += __shfl_xor_sync(0xffffffffu, sum0, 1);
        sum0 += __shfl_xor_sync(0xffffffffu, sum0, 2);
        sum1 += __shfl_xor_sync(0xffffffffu, sum1, 1);
        sum1 += __shfl_xor_sync(0xffffffffu, sum1, 2);
        li0 = li0 * sc0 + sum0;
        li1 = li1 * sc1 + sum1;
#pragma unroll
        for (int j = 0; j < 8; j++) {
            o[j][0] *= sc0; o[j][1] *= sc0;
            o[j][2] *= sc1; o[j][3] *= sc1;
        }

#pragma unroll
        for (int j = 0; j < 8; j++) {
            Ph[(m0 + r) * QS + (j << 2) + cl]     = pack_half2(s[j][0], s[j][1]);
            Ph[(m0 + r + 8) * QS + (j << 2) + cl] = pack_half2(s[j][2], s[j][3]);
        }
        __syncwarp();

#pragma unroll
        for (int ks = 0; ks < 4; ks++) {
            int pa = (m0 + r) * QS + (ks << 3) + cl;
            uint32_t a[4];
            a[0] = Ph[pa];           a[1] = Ph[pa + 8 * QS];
            a[2] = Ph[pa + 4];       a[3] = Ph[pa + 8 * QS + 4];
#pragma unroll
            for (int j = 0; j < 8; j++) {
                int vb = ((j << 3) + r) * QS + (ks << 3) + cl;
                uint32_t b2[2];
                b2[0] = Vth[vb]; b2[1] = Vth[vb + 4];
                mma_fp16(o[j], a, b2);
            }
        }
    }

    {
        float inv0 = 1.f / li0, inv1 = 1.f / li1;
        __half* o0 = att16 + ((size_t)(b * SEQ + qb + m0 + r)) * CDIM + h * HDIM;
        __half* o1 = o0 + 8 * CDIM;
#pragma unroll
        for (int j = 0; j < 8; j++) {
            int col = (j << 3) + (cl << 1);
            *(uint32_t*)&o0[col] = pack_half2(o[j][0] * inv0, o[j][1] * inv0);
            *(uint32_t*)&o1[col] = pack_half2(o[j][2] * inv1, o[j][3] * inv1);
        }
    }
}
#define FLASH_SMEM ((128 + 128 + 64 + 64 + 64 + 128) * QS * 4)

// ---------------- launch --------------------------------------------------
extern "C" void kernel_launch(void* const* d_in, const int* in_sizes, int n_in,
                              void* d_out, int out_size) {
    const float* x     = (const float*)d_in[0];
    const float* ln1w  = (const float*)d_in[1];
    const float* ln1b  = (const float*)d_in[2];
    const float* ln2w  = (const float*)d_in[3];
    const float* ln2b  = (const float*)d_in[4];
    const float* wqkv  = (const float*)d_in[5];
    const float* wproj = (const float*)d_in[6];
    const float* wfc1  = (const float*)d_in[7];
    const float* bfc1  = (const float*)d_in[8];
    const float* wfc2  = (const float*)d_in[9];
    const float* bfc2  = (const float*)d_in[10];
    float* out = (float*)d_out;

    __half *p_h16, *p_att16, *p_fc1h, *p_wqkv_h, *p_wproj_h, *p_wfc1_h, *p_wfc2_h;
    float *p_qkv, *p_x1;
    cudaGetSymbolAddress((void**)&p_h16, g_h16);
    cudaGetSymbolAddress((void**)&p_qkv, g_qkv);
    cudaGetSymbolAddress((void**)&p_att16, g_att16);
    cudaGetSymbolAddress((void**)&p_x1, g_x1);
    cudaGetSymbolAddress((void**)&p_fc1h, g_fc1h);
    cudaGetSymbolAddress((void**)&p_wqkv_h, g_wqkv_h);
    cudaGetSymbolAddress((void**)&p_wproj_h, g_wproj_h);
    cudaGetSymbolAddress((void**)&p_wfc1_h, g_wfc1_h);
    cudaGetSymbolAddress((void**)&p_wfc2_h, g_wfc2_h);

    cudaFuncSetAttribute(flash_mma, cudaFuncAttributeMaxDynamicSharedMemorySize,
                         FLASH_SMEM);
    cudaFuncSetAttribute(gemm_fp16, cudaFuncAttributeMaxDynamicSharedMemorySize,
                         GEMM_SMEM);

    dim3 tb(32, 8);
    transpose_kernel<<<dim3(QKVC / 32, CDIM / 32), tb>>>(wqkv, p_wqkv_h, CDIM, QKVC);
    transpose_kernel<<<dim3(CDIM / 32, CDIM / 32), tb>>>(wproj, p_wproj_h, CDIM, CDIM);
    transpose_kernel<<<dim3(HID / 32, CDIM / 32), tb>>>(wfc1, p_wfc1_h, CDIM, HID);
    transpose_kernel<<<dim3(CDIM / 32, HID / 32), tb>>>(wfc2, p_wfc2_h, HID, CDIM);

    // 1) h = LN1(x)  (fp16 out)
    ln_kernel<<<TOKS, 256>>>(x, ln1w, ln1b, p_h16);
    // 2) qkv = h @ w_qkv  (fp32 out, feeds flash)
    gemm_fp16<<<dim3(QKVC / 128, TOKS / 128), 256, GEMM_SMEM>>>(
        p_h16, p_wqkv_h, p_qkv, nullptr, QKVC, CDIM, nullptr, nullptr, 0);
    // 3-5) fused attention (att out fp16)
    flash_mma<<<dim3(SEQ / 128, NBH), 256, FLASH_SMEM>>>(p_qkv, p_att16);
    // 6) x1 = x + att @ w_proj  (fp32 out)
    gemm_fp16<<<dim3(CDIM / 128, TOKS / 128), 256, GEMM_SMEM>>>(
        p_att16, p_wproj_h, p_x1, nullptr, CDIM, CDIM, nullptr, x, 0);
    // 7) h = LN2(x1)  (fp16 out)
    ln_kernel<<<TOKS, 256>>>(p_x1, ln2w, ln2b, p_h16);
    // 8) fc1 = gelu(h @ w_fc1 + b_fc1)  (fp16 out)
    gemm_fp16<<<dim3(HID / 128, TOKS / 128), 256, GEMM_SMEM>>>(
        p_h16, p_wfc1_h, nullptr, p_fc1h, HID, CDIM, bfc1, nullptr, 1);
    // 9) out = x1 + fc1 @ w_fc2 + b_fc2  (fp32 out)
    gemm_fp16<<<dim3(CDIM / 128, TOKS / 128), 256, GEMM_SMEM>>>(
        p_fc1h, p_wfc2_h, out, nullptr, CDIM, HID, bfc2, p_x1, 0);
}

// round 12
// speedup vs baseline: 2.2226x; 1.0036x over previous
#include <cuda_runtime.h>
#include <cuda_fp16.h>
#include <math.h>
#include <stddef.h>
#include <stdint.h>

// ---------------- problem constants ----------------
#define TOKS   8192
#define CDIM   768
#define HID    384
#define NHEAD  12
#define HDIM   64
#define SEQ    1024
#define QKVC   2304
#define NBH    96

// ---------------- scratch ---------------------------
__device__ __half g_h16[(size_t)TOKS * CDIM];
__device__ float  g_qkv[(size_t)TOKS * QKVC];
__device__ __half g_att16[(size_t)TOKS * CDIM];
__device__ float  g_x1[(size_t)TOKS * CDIM];
__device__ __half g_fc1h[(size_t)TOKS * HID];
__device__ __half g_wqkv_h[(size_t)QKVC * CDIM];
__device__ __half g_wproj_h[(size_t)CDIM * CDIM];
__device__ __half g_wfc1_h[(size_t)HID * CDIM];
__device__ __half g_wfc2_h[(size_t)CDIM * HID];

typedef unsigned long long u64;

// ---------------- helpers -----------------------
__device__ __forceinline__ uint32_t smem_u32(const void* p) {
    uint32_t a;
    asm("{ .reg .u64 t; cvta.to.shared.u64 t, %1; cvt.u32.u64 %0, t; }" : "=r"(a) : "l"(p));
    return a;
}
__device__ __forceinline__ void cp_async16(uint32_t dst, const void* src) {
    asm volatile("cp.async.cg.shared.global [%0], [%1], 16;" :: "r"(dst), "l"(src));
}
#define CP_COMMIT() asm volatile("cp.async.commit_group;" ::: "memory")

__device__ __forceinline__ void sts16(uint32_t a, unsigned short v) {
    asm volatile("st.shared.u16 [%0], %1;" :: "r"(a), "h"(v));
}
__device__ __forceinline__ void ldsm_x4(uint32_t addr, uint32_t &r0, uint32_t &r1,
                                        uint32_t &r2, uint32_t &r3) {
    asm volatile("ldmatrix.sync.aligned.m8n8.x4.shared.b16 {%0,%1,%2,%3}, [%4];"
                 : "=r"(r0), "=r"(r1), "=r"(r2), "=r"(r3) : "r"(addr));
}

__device__ __forceinline__ void mma_fp16(float* d, const uint32_t* a, const uint32_t* b) {
    asm volatile(
        "mma.sync.aligned.m16n8k16.row.col.f32.f16.f16.f32 "
        "{%0,%1,%2,%3}, {%4,%5,%6,%7}, {%8,%9}, {%0,%1,%2,%3};"
        : "+f"(d[0]), "+f"(d[1]), "+f"(d[2]), "+f"(d[3])
        : "r"(a[0]), "r"(a[1]), "r"(a[2]), "r"(a[3]), "r"(b[0]), "r"(b[1]));
}
__device__ __forceinline__ void mma_bf16(float* d, const uint32_t* a, const uint32_t* b) {
    asm volatile(
        "mma.sync.aligned.m16n8k16.row.col.f32.bf16.bf16.f32 "
        "{%0,%1,%2,%3}, {%4,%5,%6,%7}, {%8,%9}, {%0,%1,%2,%3};"
        : "+f"(d[0]), "+f"(d[1]), "+f"(d[2]), "+f"(d[3])
        : "r"(a[0]), "r"(a[1]), "r"(a[2]), "r"(a[3]), "r"(b[0]), "r"(b[1]));
}

__device__ __forceinline__ uint32_t pack_bf16x2(float lo_e, float hi_e) {
    uint32_t r;
    asm("cvt.rn.bf16x2.f32 %0, %1, %2;" : "=r"(r) : "f"(hi_e), "f"(lo_e));
    return r;
}
__device__ __forceinline__ uint32_t pack_half2(float lo_e, float hi_e) {
    uint32_t r;
    asm("cvt.rn.f16x2.f32 %0, %1, %2;" : "=r"(r) : "f"(hi_e), "f"(lo_e));
    return r;
}
__device__ __forceinline__ void split_bf16(float x, float y, uint32_t &hp, uint32_t &lp) {
    hp = pack_bf16x2(x, y);
    float hx = __uint_as_float(hp << 16);
    float hy = __uint_as_float(hp & 0xffff0000u);
    lp = pack_bf16x2(x - hx, y - hy);
}

// ---------------- weight transpose+convert: out[n][k] = fp16(in[k][n]) ----
__global__ void transpose_kernel(const float* __restrict__ in, __half* __restrict__ out,
                                 int K, int N) {
    __shared__ float t[32][33];
    int bn = blockIdx.x << 5, bk = blockIdx.y << 5;
    int tx = threadIdx.x, ty = threadIdx.y;   // 32 x 8
#pragma unroll
    for (int i = 0; i < 4; i++)
        t[ty + i * 8][tx] = in[(size_t)(bk + ty + i * 8) * N + bn + tx];
    __syncthreads();
#pragma unroll
    for (int i = 0; i < 4; i++)
        out[(size_t)(bn + ty + i * 8) * K + bk + tx] = __float2half_rn(t[tx][ty + i * 8]);
}

// ---------------- LayerNorm (fp32 in -> fp16 out) -------------------------
__global__ void ln_kernel(const float* __restrict__ x, const float* __restrict__ w,
                          const float* __restrict__ b, __half* __restrict__ out) {
    int row = blockIdx.x;
    const float* xr = x + (size_t)row * CDIM;
    __half* orow = out + (size_t)row * CDIM;
    int t = threadIdx.x;
    float v0 = xr[t], v1 = xr[t + 256], v2 = xr[t + 512];
    float s = v0 + v1 + v2;
    float q = v0 * v0 + v1 * v1 + v2 * v2;
#pragma unroll
    for (int o = 16; o; o >>= 1) {
        s += __shfl_xor_sync(0xffffffffu, s, o);
        q += __shfl_xor_sync(0xffffffffu, q, o);
    }
    __shared__ float rs[8], rq[8];
    if ((t & 31) == 0) { rs[t >> 5] = s; rq[t >> 5] = q; }
    __syncthreads();
    if (t < 32) {
        float us = (t < 8) ? rs[t] : 0.f;
        float uq = (t < 8) ? rq[t] : 0.f;
#pragma unroll
        for (int o = 4; o; o >>= 1) {
            us += __shfl_xor_sync(0xffffffffu, us, o);
            uq += __shfl_xor_sync(0xffffffffu, uq, o);
        }
        if (t == 0) { rs[0] = us; rq[0] = uq; }
    }
    __syncthreads();
    float mu  = rs[0] * (1.f / CDIM);
    float var = rq[0] * (1.f / CDIM) - mu * mu;
    float inv = rsqrtf(var + 1e-5f);
    orow[t]       = __float2half_rn((v0 - mu) * inv * w[t]       + b[t]);
    orow[t + 256] = __float2half_rn((v1 - mu) * inv * w[t + 256] + b[t + 256]);
    orow[t + 512] = __float2half_rn((v2 - mu) * inv * w[t + 512] + b[t + 512]);
}

// ---------------- fp16 GEMM with ldmatrix fragments (R11, verbatim) -------
#define GSTG 16384u
__global__ void __launch_bounds__(256)
gemm_fp16(const __half* __restrict__ A, const __half* __restrict__ Bt,
          float* __restrict__ C, __half* __restrict__ C16, int N, int K,
          const float* __restrict__ bias, const float* __restrict__ resid,
          int gelu_flag) {
    extern __shared__ char smem[];
    const uint32_t sb = smem_u32(smem);
    const int tid = threadIdx.x;
    const int wid = tid >> 5, lane = tid & 31;
    const int warp_m = wid & 1, warp_n = wid >> 1;
    const int cl = lane & 3;
    const int g  = lane >> 2;
    const int bn = blockIdx.x << 7, bm = blockIdx.y << 7;
    const int nBK = K >> 5;

    float d[4][4][4];
#pragma unroll
    for (int i = 0; i < 4; i++)
#pragma unroll
        for (int j = 0; j < 4; j++)
#pragma unroll
            for (int e = 0; e < 4; e++) d[i][j][e] = 0.f;

#define LOADT(k0, buf)                                                          \
    {                                                                           \
        uint32_t base = sb + ((buf) ? GSTG : 0u);                               \
        _Pragma("unroll")                                                       \
        for (int i = 0; i < 2; i++) {                                           \
            int id = tid + (i << 8);                                            \
            int row = id >> 2, kh = id & 3;                                     \
            uint32_t dst = base + (uint32_t)(row << 6)                          \
                         + (uint32_t)((kh ^ ((row >> 1) & 3)) << 4);            \
            cp_async16(dst, A + (size_t)(bm + row) * K + (k0) + (kh << 3));     \
            cp_async16(dst + 8192u,                                             \
                       Bt + (size_t)(bn + row) * K + (k0) + (kh << 3));         \
        }                                                                       \
        CP_COMMIT();                                                            \
    }

    LOADT(0, 0);
    if (nBK > 1) LOADT(32, 1);

    const int ar  = (lane & 7) + (((lane >> 3) & 1) << 3);
    const int khp = lane >> 4;
    const int rowa = warp_m * 64 + ar;
    const int rowb = warp_n * 32 + ar;
    const uint32_t swa = (uint32_t)((rowa >> 1) & 3);
    const uint32_t swb = (uint32_t)((rowb >> 1) & 3);

    for (int c = 0; c < nBK; c++) {
        int buf = c & 1;
        if (c == nBK - 1) asm volatile("cp.async.wait_group 0;" ::: "memory");
        else              asm volatile("cp.async.wait_group 1;" ::: "memory");
        __syncthreads();

        const uint32_t Sb = sb + (buf ? GSTG : 0u);
        const uint32_t Ab = Sb + (uint32_t)(rowa << 6);
        const uint32_t Bb = Sb + 8192u + (uint32_t)(rowb << 6);

#pragma unroll
        for (int ks = 0; ks < 2; ks++) {
            uint32_t kha = (uint32_t)(((2 * ks + khp) ^ swa) << 4);
            uint32_t khb = (uint32_t)(((2 * ks + khp) ^ swb) << 4);
            uint32_t av[4][4], bv[4][2];
#pragma unroll
            for (int mi = 0; mi < 4; mi++)
                ldsm_x4(Ab + (uint32_t)(mi << 10) + kha,
                        av[mi][0], av[mi][1], av[mi][2], av[mi][3]);
#pragma unroll
            for (int j2 = 0; j2 < 2; j2++)
                ldsm_x4(Bb + (uint32_t)(j2 << 10) + khb,
                        bv[j2 * 2][0], bv[j2 * 2 + 1][0],
                        bv[j2 * 2][1], bv[j2 * 2 + 1][1]);
#pragma unroll
            for (int i = 0; i < 4; i++)
#pragma unroll
                for (int j = 0; j < 4; j++) mma_fp16(d[i][j], av[i], bv[j]);
        }
        __syncthreads();
        if (c + 2 < nBK) LOADT((c + 2) << 5, buf);
    }

    const int m0w = bm + warp_m * 64 + g;
    const int n0w = bn + warp_n * 32 + cl * 2;
#pragma unroll
    for (int i = 0; i < 4; i++) {
#pragma unroll
        for (int h = 0; h < 2; h++) {
            int row = m0w + i * 16 + h * 8;
            const float* Rrow = resid ? resid + (size_t)row * N : (const float*)0;
#pragma unroll
            for (int j = 0; j < 4; j++) {
                int col = n0w + j * 8;
                float v0 = d[i][j][h * 2 + 0];
                float v1 = d[i][j][h * 2 + 1];
                if (bias) { v0 += bias[col]; v1 += bias[col + 1]; }
                if (gelu_flag) {
                    v0 = 0.5f * v0 * (1.f + erff(v0 * 0.70710678118654752f));
                    v1 = 0.5f * v1 * (1.f + erff(v1 * 0.70710678118654752f));
                }
                if (Rrow) { v0 += Rrow[col]; v1 += Rrow[col + 1]; }
                if (C16) {
                    *(uint32_t*)&C16[(size_t)row * N + col] = pack_half2(v0, v1);
                } else {
                    *(float2*)&C[(size_t)row * N + col] = make_float2(v0, v1);
                }
            }
        }
    }
#undef LOADT
}
#define GEMM_SMEM (2 * 16384)

// ---------------- flash attention: ldmatrix fragment loads ----------------
// Identical math/layout/syncs to R10/R11; only fragment loads switch from
// scalar LDS.32 to ldmatrix.x4 (240 -> 60 load instructions per warp-tile).
// Row stride QS=36 u32 = 144B == 4 banks mod 32 -> all 8-lane ldmatrix
// phases hit distinct bank-groups (conflict-free).
#define QS 36
#define QSB 144u

__global__ void __launch_bounds__(256, 1)
flash_mma(const float* __restrict__ qkv, __half* __restrict__ att16) {
    extern __shared__ char smc[];
    uint32_t* Qhb = (uint32_t*)smc;            // [128][QS]
    uint32_t* Qlb = Qhb + 128 * QS;            // [128][QS]
    uint32_t* Khb = Qlb + 128 * QS;            // [64][QS]
    uint32_t* Klb = Khb + 64 * QS;             // [64][QS]
    uint32_t* Vth = Klb + 64 * QS;             // [64 d][QS] fp16 kv-pairs
    uint32_t* Ph  = Vth + 64 * QS;             // [128 q][QS] fp16 kv-pairs

    const int tid = threadIdx.x;
    const int wid = tid >> 5, lane = tid & 31;
    const int r = lane >> 2, cl = lane & 3;
    const int qb = blockIdx.x << 7;
    const int bh = blockIdx.y;
    const int b = bh / NHEAD, h = bh % NHEAD;
    const float* qptr = qkv + (size_t)b * SEQ * QKVC + h * HDIM;
    const float* kptr = qptr + CDIM;
    const float* vptr = qptr + 2 * CDIM;
    const uint32_t vth_sb = smem_u32(Vth);

    // ---- load Q (x8 scale), split bf16 hi/lo pairs ----
    {
        int row = tid >> 1;
        const float* src = qptr + (size_t)(qb + row) * QKVC;
#pragma unroll
        for (int e = 0; e < 8; e++) {
            int c4 = ((tid & 1) << 3) + e;
            float4 v = *(const float4*)(src + (c4 << 2));
            v.x *= 8.f; v.y *= 8.f; v.z *= 8.f; v.w *= 8.f;
            uint32_t h0, l0, h1, l1;
            split_bf16(v.x, v.y, h0, l0);
            split_bf16(v.z, v.w, h1, l1);
            Qhb[row * QS + 2 * c4]     = h0;
            Qhb[row * QS + 2 * c4 + 1] = h1;
            Qlb[row * QS + 2 * c4]     = l0;
            Qlb[row * QS + 2 * c4 + 1] = l1;
        }
    }

    float mi0 = -3.4e38f, mi1 = -3.4e38f, li0 = 0.f, li1 = 0.f;
    float o[8][4];
#pragma unroll
    for (int j = 0; j < 8; j++)
#pragma unroll
        for (int e = 0; e < 4; e++) o[j][e] = 0.f;

    const int m0 = wid << 4;
    // ldmatrix lane geometry
    const int fr8 = (lane & 7) + (((lane >> 3) & 1) << 3);   // row within 16
    const uint32_t khf16 = (uint32_t)(lane >> 4) << 4;       // k-half byte off
    const uint32_t qoff  = (uint32_t)(m0 + fr8) * QSB + khf16;
    const uint32_t koff0 = (uint32_t)fr8 * QSB + khf16;
    const uint32_t qh_b = smem_u32(Qhb) + qoff;
    const uint32_t ql_b = smem_u32(Qlb) + qoff;
    const uint32_t kh_b = smem_u32(Khb) + koff0;
    const uint32_t kl_b = smem_u32(Klb) + koff0;
    const uint32_t ph_b = smem_u32(Ph) + qoff;
    const uint32_t vt_b = vth_sb + koff0;

    for (int t = 0; t < 16; t++) {
        __syncthreads();   // prior PV done before overwriting K/V
        // ---- load K (bf16 hi/lo) and V (fp16 pairs, transposed) ----
        {
            int row = tid >> 2;
            const float* ksrc = kptr + (size_t)((t << 6) + row) * QKVC;
            const float* vsrc = vptr + (size_t)((t << 6) + row) * QKVC;
            uint32_t vbase = vth_sb + (uint32_t)((row >> 1) << 2) + ((row & 1) << 1);
#pragma unroll
            for (int e = 0; e < 4; e++) {
                int c4 = (tid & 3) + (e << 2);
                float4 v = *(const float4*)(ksrc + (c4 << 2));
                uint32_t h0, l0, h1, l1;
                split_bf16(v.x, v.y, h0, l0);
                split_bf16(v.z, v.w, h1, l1);
                Khb[row * QS + 2 * c4]     = h0;
                Khb[row * QS + 2 * c4 + 1] = h1;
                Klb[row * QS + 2 * c4]     = l0;
                Klb[row * QS + 2 * c4 + 1] = l1;
                float4 vv = *(const float4*)(vsrc + (c4 << 2));
                int dc = c4 << 2;
                sts16(vbase + (uint32_t)((dc + 0) * QS << 2),
                      __half_as_ushort(__float2half_rn(vv.x)));
                sts16(vbase + (uint32_t)((dc + 1) * QS << 2),
                      __half_as_ushort(__float2half_rn(vv.y)));
                sts16(vbase + (uint32_t)((dc + 2) * QS << 2),
                      __half_as_ushort(__float2half_rn(vv.z)));
                sts16(vbase + (uint32_t)((dc + 3) * QS << 2),
                      __half_as_ushort(__float2half_rn(vv.w)));
            }
        }
        __syncthreads();

        // ---- S = Q K^T (bf16x3, m16n8k16), ldmatrix fragments ----
        float s[8][4];
#pragma unroll
        for (int j = 0; j < 8; j++)
#pragma unroll
            for (int e = 0; e < 4; e++) s[j][e] = 0.f;

#pragma unroll
        for (int ks = 0; ks < 4; ks++) {
            uint32_t ko = (uint32_t)(ks << 5);
            uint32_t ah[4], al[4];
            ldsm_x4(qh_b + ko, ah[0], ah[1], ah[2], ah[3]);
            ldsm_x4(ql_b + ko, al[0], al[1], al[2], al[3]);
#pragma unroll
            for (int jp = 0; jp < 4; jp++) {
                uint32_t jo = (uint32_t)(jp * 16) * QSB + ko;
                uint32_t bh2[2][2], bl2[2][2];
                ldsm_x4(kh_b + jo, bh2[0][0], bh2[1][0], bh2[0][1], bh2[1][1]);
                ldsm_x4(kl_b + jo, bl2[0][0], bl2[1][0], bl2[0][1], bl2[1][1]);
#pragma unroll
                for (int jj = 0; jj < 2; jj++) {
                    int j = jp * 2 + jj;
                    mma_bf16(s[j], ah, bh2[jj]);
                    mma_bf16(s[j], al, bh2[jj]);
                    mma_bf16(s[j], ah, bl2[jj]);
                }
            }
        }

        // ---- online softmax (rows m0+r and m0+r+8) ----
        float mx0 = s[0][0], mx1 = s[0][2];
#pragma unroll
        for (int j = 0; j < 8; j++) {
            mx0 = fmaxf(mx0, fmaxf(s[j][0], s[j][1]));
            mx1 = fmaxf(mx1, fmaxf(s[j][2], s[j][3]));
        }
        mx0 = fmaxf(mx0, __shfl_xor_sync(0xffffffffu, mx0, 1));
        mx0 = fmaxf(mx0, __shfl_xor_sync(0xffffffffu, mx0, 2));
        mx1 = fmaxf(mx1, __shfl_xor_sync(0xffffffffu, mx1, 1));
        mx1 = fmaxf(mx1, __shfl_xor_sync(0xffffffffu, mx1, 2));
        float mn0 = fmaxf(mi0, mx0), mn1 = fmaxf(mi1, mx1);
        float sc0 = __expf(mi0 - mn0), sc1 = __expf(mi1 - mn1);
        mi0 = mn0; mi1 = mn1;
        float sum0 = 0.f, sum1 = 0.f;
#pragma unroll
        for (int j = 0; j < 8; j++) {
            s[j][0] = __expf(s[j][0] - mn0);
            s[j][1] = __expf(s[j][1] - mn0);
            s[j][2] = __expf(s[j][2] - mn1);
            s[j][3] = __expf(s[j][3] - mn1);
            sum0 += s[j][0] + s[j][1];
            sum1 += s[j][2] + s[j][3];
        }
        sum0 += __shfl_xor_sync(0xffffffffu, sum0, 1);
        sum0 += __shfl_xor_sync(0xffffffffu, sum0, 2);
        sum1 += __shfl_xor_sync(0xffffffffu, sum1, 1);
        sum1 += __shfl_xor_sync(0xffffffffu, sum1, 2);
        li0 = li0 * sc0 + sum0;
        li1 = li1 * sc1 + sum1;
#pragma unroll
        for (int j = 0; j < 8; j++) {
            o[j][0] *= sc0; o[j][1] *= sc0;
            o[j][2] *= sc1; o[j][3] *= sc1;
        }

        // ---- store P as fp16 pairs ----
#pragma unroll
        for (int j = 0; j < 8; j++) {
            Ph[(m0 + r) * QS + (j << 2) + cl]     = pack_half2(s[j][0], s[j][1]);
            Ph[(m0 + r + 8) * QS + (j << 2) + cl] = pack_half2(s[j][2], s[j][3]);
        }
        __syncwarp();

        // ---- O += P @ V (fp16 m16n8k16), ldmatrix fragments ----
#pragma unroll
        for (int ks = 0; ks < 4; ks++) {
            uint32_t ko = (uint32_t)(ks << 5);
            uint32_t a[4];
            ldsm_x4(ph_b + ko, a[0], a[1], a[2], a[3]);
#pragma unroll
            for (int jp = 0; jp < 4; jp++) {
                uint32_t jo = (uint32_t)(jp * 16) * QSB + ko;
                uint32_t b2[2][2];
                ldsm_x4(vt_b + jo, b2[0][0], b2[1][0], b2[0][1], b2[1][1]);
                mma_fp16(o[jp * 2 + 0], a, b2[0]);
                mma_fp16(o[jp * 2 + 1], a, b2[1]);
            }
        }
    }

    // ---- epilogue: O / l -> att16 in [B,N,C] ----
    {
        float inv0 = 1.f / li0, inv1 = 1.f / li1;
        __half* o0 = att16 + ((size_t)(b * SEQ + qb + m0 + r)) * CDIM + h * HDIM;
        __half* o1 = o0 + 8 * CDIM;
#pragma unroll
        for (int j = 0; j < 8; j++) {
            int col = (j << 3) + (cl << 1);
            *(uint32_t*)&o0[col] = pack_half2(o[j][0] * inv0, o[j][1] * inv0);
            *(uint32_t*)&o1[col] = pack_half2(o[j][2] * inv1, o[j][3] * inv1);
        }
    }
}
#define FLASH_SMEM ((128 + 128 + 64 + 64 + 64 + 128) * QS * 4)

// ---------------- launch --------------------------------------------------
extern "C" void kernel_launch(void* const* d_in, const int* in_sizes, int n_in,
                              void* d_out, int out_size) {
    const float* x     = (const float*)d_in[0];
    const float* ln1w  = (const float*)d_in[1];
    const float* ln1b  = (const float*)d_in[2];
    const float* ln2w  = (const float*)d_in[3];
    const float* ln2b  = (const float*)d_in[4];
    const float* wqkv  = (const float*)d_in[5];
    const float* wproj = (const float*)d_in[6];
    const float* wfc1  = (const float*)d_in[7];
    const float* bfc1  = (const float*)d_in[8];
    const float* wfc2  = (const float*)d_in[9];
    const float* bfc2  = (const float*)d_in[10];
    float* out = (float*)d_out;

    __half *p_h16, *p_att16, *p_fc1h, *p_wqkv_h, *p_wproj_h, *p_wfc1_h, *p_wfc2_h;
    float *p_qkv, *p_x1;
    cudaGetSymbolAddress((void**)&p_h16, g_h16);
    cudaGetSymbolAddress((void**)&p_qkv, g_qkv);
    cudaGetSymbolAddress((void**)&p_att16, g_att16);
    cudaGetSymbolAddress((void**)&p_x1, g_x1);
    cudaGetSymbolAddress((void**)&p_fc1h, g_fc1h);
    cudaGetSymbolAddress((void**)&p_wqkv_h, g_wqkv_h);
    cudaGetSymbolAddress((void**)&p_wproj_h, g_wproj_h);
    cudaGetSymbolAddress((void**)&p_wfc1_h, g_wfc1_h);
    cudaGetSymbolAddress((void**)&p_wfc2_h, g_wfc2_h);

    cudaFuncSetAttribute(flash_mma, cudaFuncAttributeMaxDynamicSharedMemorySize,
                         FLASH_SMEM);
    cudaFuncSetAttribute(gemm_fp16, cudaFuncAttributeMaxDynamicSharedMemorySize,
                         GEMM_SMEM);

    dim3 tb(32, 8);
    transpose_kernel<<<dim3(QKVC / 32, CDIM / 32), tb>>>(wqkv, p_wqkv_h, CDIM, QKVC);
    transpose_kernel<<<dim3(CDIM / 32, CDIM / 32), tb>>>(wproj, p_wproj_h, CDIM, CDIM);
    transpose_kernel<<<dim3(HID / 32, CDIM / 32), tb>>>(wfc1, p_wfc1_h, CDIM, HID);
    transpose_kernel<<<dim3(CDIM / 32, HID / 32), tb>>>(wfc2, p_wfc2_h, HID, CDIM);

    // 1) h = LN1(x)  (fp16 out)
    ln_kernel<<<TOKS, 256>>>(x, ln1w, ln1b, p_h16);
    // 2) qkv = h @ w_qkv  (fp32 out, feeds flash)
    gemm_fp16<<<dim3(QKVC / 128, TOKS / 128), 256, GEMM_SMEM>>>(
        p_h16, p_wqkv_h, p_qkv, nullptr, QKVC, CDIM, nullptr, nullptr, 0);
    // 3-5) fused attention (att out fp16)
    flash_mma<<<dim3(SEQ / 128, NBH), 256, FLASH_SMEM>>>(p_qkv, p_att16);
    // 6) x1 = x + att @ w_proj  (fp32 out)
    gemm_fp16<<<dim3(CDIM / 128, TOKS / 128), 256, GEMM_SMEM>>>(
        p_att16, p_wproj_h, p_x1, nullptr, CDIM, CDIM, nullptr, x, 0);
    // 7) h = LN2(x1)  (fp16 out)
    ln_kernel<<<TOKS, 256>>>(p_x1, ln2w, ln2b, p_h16);
    // 8) fc1 = gelu(h @ w_fc1 + b_fc1)  (fp16 out)
    gemm_fp16<<<dim3(HID / 128, TOKS / 128), 256, GEMM_SMEM>>>(
        p_h16, p_wfc1_h, nullptr, p_fc1h, HID, CDIM, bfc1, nullptr, 1);
    // 9) out = x1 + fc1 @ w_fc2 + b_fc2  (fp32 out)
    gemm_fp16<<<dim3(CDIM / 128, TOKS / 128), 256, GEMM_SMEM>>>(
        p_fc1h, p_wfc2_h, out, nullptr, CDIM, HID, bfc2, p_x1, 0);
}